// round 10
// baseline (speedup 1.0000x reference)
#include <cuda_runtime.h>
#include <cuda_bf16.h>
#include <cstdint>

#define TT 512
#define BB 32
#define II 1024
#define HH 1024
#define G4 4096   // 4*H
#define NB 128    // persistent CTAs
#define NTH 512   // threads per CTA (recurrence)

#define KCH 48          // K' chunks of 64 (3*1024/64)
#define MT  128         // M tiles (16384/128)
#define NTB 32          // N tiles (4096/128)
#define GT_A 16384
#define GT_B 16384
#define GSTAGE_B (GT_A + GT_B)
#define GSTG 3

// recurrence smem offsets (bytes)
#define RS_H 0
#define RS_L 65536
#define YSM  131072                 // [2 buf][ hi 16K | lo 16K ]
#define REDO 196608                 // red [8 warp][4][32] floats = 4KB
#define GSMO 200704                 // gsm [32][33] floats = 4224B
#define SMEM_REC (GSMO + 32 * 33 * 4)

// ------------------------- device scratch -------------------------
__device__ float g_gates[(size_t)TT * BB * G4];                 // 256 MB
__device__ unsigned char g_At[(size_t)KCH * MT * GT_A];
__device__ unsigned char g_Bt[(size_t)KCH * NTB * GT_B];
__device__ __nv_bfloat16 g_yh[2][BB * HH];   // y hi, [buf][b][k]
__device__ __nv_bfloat16 g_yl[2][BB * HH];   // y lo
__device__ unsigned g_count;

// ------------------------- helpers -------------------------
__device__ __forceinline__ uint32_t smem_u32(const void* p) {
    uint32_t a;
    asm("{ .reg .u64 t; cvta.to.shared.u64 t, %1; cvt.u32.u64 %0, t; }" : "=r"(a) : "l"(p));
    return a;
}
__device__ __forceinline__ void ldsm4(uint32_t (&r)[4], uint32_t addr) {
    asm volatile("ldmatrix.sync.aligned.m8n8.x4.shared.b16 {%0,%1,%2,%3}, [%4];"
        : "=r"(r[0]), "=r"(r[1]), "=r"(r[2]), "=r"(r[3]) : "r"(addr));
}
__device__ __forceinline__ void ldsm2(uint32_t (&r)[2], uint32_t addr) {
    asm volatile("ldmatrix.sync.aligned.m8n8.x2.shared.b16 {%0,%1}, [%2];"
        : "=r"(r[0]), "=r"(r[1]) : "r"(addr));
}
__device__ __forceinline__ void mma16816(float (&d)[4], const uint32_t (&a)[4],
                                         uint32_t b0, uint32_t b1) {
    asm volatile("mma.sync.aligned.m16n8k16.row.col.f32.bf16.bf16.f32 "
        "{%0,%1,%2,%3}, {%4,%5,%6,%7}, {%8,%9}, {%0,%1,%2,%3};"
        : "+f"(d[0]), "+f"(d[1]), "+f"(d[2]), "+f"(d[3])
        : "r"(a[0]), "r"(a[1]), "r"(a[2]), "r"(a[3]), "r"(b0), "r"(b1));
}
__device__ __forceinline__ void cp16(uint32_t sdst, const void* gsrc) {
    asm volatile("cp.async.cg.shared.global [%0], [%1], 16;" :: "r"(sdst), "l"(gsrc) : "memory");
}
__device__ __forceinline__ void cp_commit() {
    asm volatile("cp.async.commit_group;" ::: "memory");
}
template<int N> __device__ __forceinline__ void cp_wait() {
    asm volatile("cp.async.wait_group %0;" :: "n"(N) : "memory");
}
__device__ __forceinline__ uint32_t pack_bf2(float a, float b) {
    __nv_bfloat162 h = __floats2bfloat162_rn(a, b);
    return *(uint32_t*)&h;
}
__device__ __forceinline__ float hsig(float v) {
    return __saturatef(v * 0.16666666666666666f + 0.5f);
}
__device__ __forceinline__ float htanh(float v) {
    return fminf(fmaxf(v, -1.f), 1.f);
}

// ------------------------------------------------------------------
// Conversion kernels (unchanged)
// ------------------------------------------------------------------
__global__ __launch_bounds__(256) void convA(const float* __restrict__ x)
{
    int t = blockIdx.x * 256 + threadIdx.x;
    int cg = t & 7;
    int kc = (t >> 3) & 15;
    int m  = t >> 7;

    const float4* xp = (const float4*)(x + (size_t)m * II + kc * 64 + cg * 8);
    float4 v0 = xp[0], v1 = xp[1];
    float f[8] = {v0.x, v0.y, v0.z, v0.w, v1.x, v1.y, v1.z, v1.w};
    float hif[8], lof[8];
#pragma unroll
    for (int i = 0; i < 8; i++) {
        __nv_bfloat16 h = __float2bfloat16_rn(f[i]);
        hif[i] = __bfloat162float(h);
        lof[i] = f[i] - hif[i];
    }
    uint4 hi4 = {pack_bf2(hif[0], hif[1]), pack_bf2(hif[2], hif[3]),
                 pack_bf2(hif[4], hif[5]), pack_bf2(hif[6], hif[7])};
    uint4 lo4 = {pack_bf2(lof[0], lof[1]), pack_bf2(lof[2], lof[3]),
                 pack_bf2(lof[4], lof[5]), pack_bf2(lof[6], lof[7])};

    int mt = m >> 7, r = m & 127;
    uint32_t off = (uint32_t)r * 128 + cg * 16;
    uint32_t sw  = off ^ ((off >> 3) & 0x70);

    *(uint4*)(g_At + ((size_t)(kc +  0) * MT + mt) * GT_A + sw) = hi4;
    *(uint4*)(g_At + ((size_t)(kc + 16) * MT + mt) * GT_A + sw) = hi4;
    *(uint4*)(g_At + ((size_t)(kc + 32) * MT + mt) * GT_A + sw) = lo4;
}

__global__ __launch_bounds__(256) void convB(const float* __restrict__ W)
{
    int t = blockIdx.x * 256 + threadIdx.x;
    int cg = t & 7;
    int kc = (t >> 3) & 15;
    int n  = t >> 7;

    const float4* wp = (const float4*)(W + (size_t)n * II + kc * 64 + cg * 8);
    float4 v0 = wp[0], v1 = wp[1];
    float f[8] = {v0.x, v0.y, v0.z, v0.w, v1.x, v1.y, v1.z, v1.w};
    float hif[8], lof[8];
#pragma unroll
    for (int i = 0; i < 8; i++) {
        __nv_bfloat16 h = __float2bfloat16_rn(f[i]);
        hif[i] = __bfloat162float(h);
        lof[i] = f[i] - hif[i];
    }
    uint4 hi4 = {pack_bf2(hif[0], hif[1]), pack_bf2(hif[2], hif[3]),
                 pack_bf2(hif[4], hif[5]), pack_bf2(hif[6], hif[7])};
    uint4 lo4 = {pack_bf2(lof[0], lof[1]), pack_bf2(lof[2], lof[3]),
                 pack_bf2(lof[4], lof[5]), pack_bf2(lof[6], lof[7])};

    int nt = n >> 7, r = n & 127;
    uint32_t off = (uint32_t)r * 128 + cg * 16;
    uint32_t sw  = off ^ ((off >> 3) & 0x70);

    *(uint4*)(g_Bt + ((size_t)(kc +  0) * NTB + nt) * GT_B + sw) = hi4;
    *(uint4*)(g_Bt + ((size_t)(kc + 16) * NTB + nt) * GT_B + sw) = lo4;
    *(uint4*)(g_Bt + ((size_t)(kc + 32) * NTB + nt) * GT_B + sw) = hi4;
}

// ------------------------------------------------------------------
// HMMA pre-GEMM. Grid: x = nt (fast), y = mt -> waves share A tiles.
// ------------------------------------------------------------------
__device__ __forceinline__ void load_stage(uint32_t sbase, int s, int c, int mt, int nt, int tid)
{
    uint32_t smA = sbase + s * GSTAGE_B;
    uint32_t smB = smA + GT_A;
    const unsigned char* gA = g_At + ((size_t)c * MT + mt) * GT_A;
    const unsigned char* gB = g_Bt + ((size_t)c * NTB + nt) * GT_B;
#pragma unroll
    for (int i = 0; i < 4; i++) {
        uint32_t off = (uint32_t)(tid + i * 256) * 16;
        cp16(smA + off, gA + off);
    }
#pragma unroll
    for (int i = 0; i < 4; i++) {
        uint32_t off = (uint32_t)(tid + i * 256) * 16;
        cp16(smB + off, gB + off);
    }
}

__global__ __launch_bounds__(256, 2) void gemm_mma(const float* __restrict__ bW,
                                                   const float* __restrict__ bR)
{
    extern __shared__ __align__(128) unsigned char smg[];
    const uint32_t sbase = smem_u32(smg);

    const int tid  = threadIdx.x;
    const int lane = tid & 31;
    const int warp = tid >> 5;
    const int wm   = warp & 3;
    const int wn   = warp >> 2;
    const int nt   = blockIdx.x;
    const int mt   = blockIdx.y;

    float acc[2][8][4];
#pragma unroll
    for (int i = 0; i < 2; i++)
#pragma unroll
        for (int j = 0; j < 8; j++)
#pragma unroll
            for (int q = 0; q < 4; q++) acc[i][j][q] = 0.f;

    load_stage(sbase, 0, 0, mt, nt, tid); cp_commit();
    load_stage(sbase, 1, 1, mt, nt, tid); cp_commit();

    const int rl = lane & 15;
    const int chalf = lane >> 4;

#pragma unroll 1
    for (int c = 0; c < KCH; c++) {
        if (c + 2 < KCH) load_stage(sbase, (c + 2) % GSTG, c + 2, mt, nt, tid);
        cp_commit();
        cp_wait<2>();
        __syncthreads();

        const uint32_t smA = sbase + (c % GSTG) * GSTAGE_B;
        const uint32_t smB = smA + GT_A;

#pragma unroll
        for (int ks = 0; ks < 4; ks++) {
            const int kb = ks * 32 + chalf * 16;
            uint32_t a[2][4];
#pragma unroll
            for (int i = 0; i < 2; i++) {
                uint32_t off = (uint32_t)(wm * 32 + i * 16 + rl) * 128 + kb;
                ldsm4(a[i], smA + (off ^ ((off >> 3) & 0x70)));
            }
            uint32_t b[4][4];
#pragma unroll
            for (int j = 0; j < 4; j++) {
                uint32_t off = (uint32_t)(wn * 64 + j * 16 + rl) * 128 + kb;
                ldsm4(b[j], smB + (off ^ ((off >> 3) & 0x70)));
            }
#pragma unroll
            for (int i = 0; i < 2; i++)
#pragma unroll
                for (int j = 0; j < 4; j++) {
                    mma16816(acc[i][2 * j + 0], a[i], b[j][0], b[j][2]);
                    mma16816(acc[i][2 * j + 1], a[i], b[j][1], b[j][3]);
                }
        }
        __syncthreads();
    }

    const int m0  = mt * 128 + wm * 32 + (lane >> 2);
    const int n0g = nt * 128 + wn * 64;
#pragma unroll
    for (int i = 0; i < 2; i++) {
#pragma unroll
        for (int j = 0; j < 8; j++) {
            int n = n0g + j * 8 + (lane & 3) * 2;
            float bx = bW[n] + bR[n];
            float by = bW[n + 1] + bR[n + 1];
            int r0 = m0 + i * 16;
            float2 o0 = {acc[i][j][0] + bx, acc[i][j][1] + by};
            float2 o1 = {acc[i][j][2] + bx, acc[i][j][3] + by};
            *(float2*)&g_gates[(size_t)r0 * G4 + n] = o0;
            *(float2*)&g_gates[(size_t)(r0 + 8) * G4 + n] = o1;
        }
    }
}

// ------------------------------------------------------------------
// Init: reset counter; y0 -> bf16 hi/lo buffers
// ------------------------------------------------------------------
__global__ __launch_bounds__(256) void init_kernel(const float* __restrict__ y0)
{
    int i = blockIdx.x * 256 + threadIdx.x;   // 0..32767
    if (i == 0) g_count = 0;
    float v = y0[i];
    __nv_bfloat16 h = __float2bfloat16_rn(v);
    g_yh[0][i] = h;
    g_yl[0][i] = __float2bfloat16_rn(v - __bfloat162float(h));
}

// ------------------------------------------------------------------
// Persistent tensor-core recurrence, 512 threads / 16 warps.
// Warp: wm = warp&1 (16 batch rows), wn = (warp>>1)&3 (8 n rows),
//       wk = warp>>3 (k half of each 256-k chunk).
// ------------------------------------------------------------------
extern __shared__ __align__(128) unsigned char smrec[];

__device__ __forceinline__ void issue_y_chunk(uint32_t sbase, int buf, int c,
                                              const __nv_bfloat16* __restrict__ yhg,
                                              const __nv_bfloat16* __restrict__ ylg,
                                              int tid)
{
#pragma unroll
    for (int i = 0; i < 4; i++) {
        int gran = tid + i * 512;              // 0..2047
        int half = gran >> 10;
        int bb   = (gran >> 5) & 31;
        int gi   = gran & 31;
        const __nv_bfloat16* src = (half ? ylg : yhg) + bb * 1024 + c * 256 + gi * 8;
        uint32_t dst = sbase + YSM + buf * 32768 + half * 16384 + bb * 512
                     + (((uint32_t)gi * 16) ^ (((uint32_t)bb & 7) << 4));
        cp16(dst, src);
    }
    cp_commit();
}

__global__ __launch_bounds__(NTH, 1) void lstm_persist(const float* __restrict__ R,
                                                       const float* __restrict__ c0,
                                                       float* __restrict__ yout,
                                                       float* __restrict__ cout)
{
    const int tid = threadIdx.x;
    const int blk = blockIdx.x;
    const uint32_t sbase = smem_u32(smrec);

    // ---- load + split + swizzle R slice into SMEM (once) ----
    for (int i = tid; i < 4096; i += NTH) {
        int rr  = i >> 7;
        int g16 = i & 127;
        int G   = (rr >> 3) * HH + blk * 8 + (rr & 7);
        const float4* p = (const float4*)(R + (size_t)G * HH + g16 * 8);
        float4 v0 = p[0], v1 = p[1];
        float f[8] = {v0.x, v0.y, v0.z, v0.w, v1.x, v1.y, v1.z, v1.w};
        float hif[8], lof[8];
#pragma unroll
        for (int j = 0; j < 8; j++) {
            __nv_bfloat16 h = __float2bfloat16_rn(f[j]);
            hif[j] = __bfloat162float(h);
            lof[j] = f[j] - hif[j];
        }
        uint4 hi4 = {pack_bf2(hif[0], hif[1]), pack_bf2(hif[2], hif[3]),
                     pack_bf2(hif[4], hif[5]), pack_bf2(hif[6], hif[7])};
        uint4 lo4 = {pack_bf2(lof[0], lof[1]), pack_bf2(lof[2], lof[3]),
                     pack_bf2(lof[4], lof[5]), pack_bf2(lof[6], lof[7])};
        uint32_t off = (uint32_t)rr * 2048 + (((uint32_t)g16 * 16) ^ (((uint32_t)rr & 7) << 4));
        *(uint4*)(smrec + RS_H + off) = hi4;
        *(uint4*)(smrec + RS_L + off) = lo4;
    }
    __syncthreads();

    const int lane = tid & 31;
    const int warp = tid >> 5;
    const int wm   = warp & 1;
    const int wn   = (warp >> 1) & 3;
    const int wk   = warp >> 3;
    const int l15  = lane & 15;
    const int chalf = lane >> 4;

    const int b  = tid >> 3;          // valid for tid<256
    const int hl = tid & 7;
    const int h  = blk * 8 + hl;

    float c_val = 0.f;
    if (tid < 256) c_val = c0[(size_t)b * HH + h];

    float* red = (float*)(smrec + REDO);           // [8 warp][4][32]
    float* gsm = (float*)(smrec + GSMO);           // [32 n][33]

    // A (y) fragment addressing
    const uint32_t arow = (uint32_t)(wm * 16 + l15);
    const uint32_t aswz = (arow & 7) << 4;
    // B (R) fragment addressing (ldsm.x2: lanes 0-15)
    const uint32_t brow = (uint32_t)(wn * 8 + (l15 & 7));
    const uint32_t bkh  = (uint32_t)((l15 >> 3) & 1);
    const uint32_t bswz = (brow & 7) << 4;
    const uint32_t rbh  = sbase + RS_H + brow * 2048;
    const uint32_t rbl  = sbase + RS_L + brow * 2048;

    for (int t = 0; t < TT; t++) {
        const int rbuf = t & 1;
        const __nv_bfloat16* yhg = g_yh[rbuf];
        const __nv_bfloat16* ylg = g_yl[rbuf];

        float gp0 = 0.f, gp1 = 0.f, gp2 = 0.f, gp3 = 0.f;
        if (tid < 256) {
            const float* gp = g_gates + (size_t)t * BB * G4 + (size_t)b * G4 + h;
            gp0 = gp[0 * HH]; gp1 = gp[1 * HH]; gp2 = gp[2 * HH]; gp3 = gp[3 * HH];
        }

        float acc[4] = {0.f, 0.f, 0.f, 0.f};

        issue_y_chunk(sbase, 0, 0, yhg, ylg, tid);

#pragma unroll
        for (int c = 0; c < 4; c++) {
            if (c < 3) {
                issue_y_chunk(sbase, (c + 1) & 1, c + 1, yhg, ylg, tid);
                cp_wait<1>();
            } else {
                cp_wait<0>();
            }
            __syncthreads();

            const uint32_t ybh = sbase + YSM + (c & 1) * 32768 + arow * 512;
            const uint32_t ybl = ybh + 16384;

#pragma unroll
            for (int s = 0; s < 8; s++) {
                const uint32_t aoff = (uint32_t)((wk * 8 + s) * 32 + chalf * 16);
                const uint32_t koff = (uint32_t)((c * 16 + wk * 8 + s) * 32 + bkh * 16);
                uint32_t ah[4], al[4], bh[2], bl[2];
                ldsm4(ah, ybh + (aoff ^ aswz));
                ldsm2(bh, rbh + (koff ^ bswz));
                ldsm2(bl, rbl + (koff ^ bswz));
                ldsm4(al, ybl + (aoff ^ aswz));
                mma16816(acc, ah, bh[0], bh[1]);
                mma16816(acc, ah, bl[0], bl[1]);
                mma16816(acc, al, bh[0], bh[1]);
            }
            __syncthreads();
        }

        // ---- k-split reduce (warp w pairs with w+8) ----
        if (wk == 1) {
            const int w8 = warp & 7;
#pragma unroll
            for (int j = 0; j < 4; j++)
                red[(w8 * 4 + j) * 32 + lane] = acc[j];
        }
        __syncthreads();
        if (wk == 0) {
            const int w8 = warp & 7;
#pragma unroll
            for (int j = 0; j < 4; j++)
                acc[j] += red[(w8 * 4 + j) * 32 + lane];
            const int mrow = wm * 16 + (lane >> 2);
            const int nb0  = wn * 8 + (lane & 3) * 2;
            gsm[(nb0 + 0) * 33 + mrow]     = acc[0];
            gsm[(nb0 + 1) * 33 + mrow]     = acc[1];
            gsm[(nb0 + 0) * 33 + mrow + 8] = acc[2];
            gsm[(nb0 + 1) * 33 + mrow + 8] = acc[3];
        }
        __syncthreads();

        // ---- gate epilogue (threads 0..255) ----
        if (tid < 256) {
            float si  = gp0 + gsm[(0 * 8 + hl) * 33 + b];
            float sf  = gp1 + gsm[(1 * 8 + hl) * 33 + b];
            float sz  = gp2 + gsm[(2 * 8 + hl) * 33 + b];
            float so4 = gp3 + gsm[(3 * 8 + hl) * 33 + b];
            float i_ = hsig(si);
            float f_ = hsig(sf);
            float z_ = htanh(sz);
            float o_ = hsig(so4);
            c_val = f_ * c_val + i_ * z_;
            float y_ = o_ * htanh(c_val);

            size_t oidx = (size_t)t * BB * HH + (size_t)b * HH + h;
            yout[oidx] = y_;
            cout[oidx] = c_val;

            __nv_bfloat16 yh = __float2bfloat16_rn(y_);
            g_yh[(t + 1) & 1][b * HH + h] = yh;
            g_yl[(t + 1) & 1][b * HH + h] = __float2bfloat16_rn(y_ - __bfloat162float(yh));
        }

        // ---- grid barrier ----
        if (t < TT - 1) {
            __syncthreads();
            if (tid == 0) {
                __threadfence();
                atomicAdd(&g_count, 1u);
                unsigned tgt = (unsigned)(NB * (t + 1));
                while (*((volatile unsigned*)&g_count) < tgt) { }
                __threadfence();
            }
            __syncthreads();
        }
    }
}

// ------------------------------------------------------------------
extern "C" void kernel_launch(void* const* d_in, const int* in_sizes, int n_in,
                              void* d_out, int out_size)
{
    const float* y0 = (const float*)d_in[0];
    const float* c0 = (const float*)d_in[1];
    const float* x  = (const float*)d_in[2];
    const float* W  = (const float*)d_in[3];
    const float* R  = (const float*)d_in[4];
    const float* bW = (const float*)d_in[5];
    const float* bR = (const float*)d_in[6];

    float* yout = (float*)d_out;
    float* cout = yout + (size_t)TT * BB * HH;

    const int smem_gemm = GSTG * GSTAGE_B;     // 98304
    cudaFuncSetAttribute(gemm_mma, cudaFuncAttributeMaxDynamicSharedMemorySize, smem_gemm);
    cudaFuncSetAttribute(lstm_persist, cudaFuncAttributeMaxDynamicSharedMemorySize, SMEM_REC);

    convA<<<8192, 256>>>(x);
    convB<<<2048, 256>>>(W);
    init_kernel<<<128, 256>>>(y0);
    gemm_mma<<<dim3(NTB, MT), 256, smem_gemm>>>(bW, bR);
    lstm_persist<<<NB, NTH, SMEM_REC>>>(R, c0, yout, cout);
}

// round 11
// speedup vs baseline: 1.0155x; 1.0155x over previous
#include <cuda_runtime.h>
#include <cuda_bf16.h>
#include <cstdint>

#define TT 512
#define BB 32
#define II 1024
#define HH 1024
#define G4 4096   // 4*H
#define NB 128    // persistent CTAs
#define NTH 256   // threads per CTA (recurrence)

#define KCH 48          // K' chunks of 64 (3*1024/64)
#define MT  128         // A blobs per chunk (16384/128)
#define NTB 32          // B blobs per chunk (4096/128)
#define GT_A 16384
#define GT_B 16384
// gemm CTA tile 256x128: stage = A 32KB + B 16KB
#define GST2 49152
#define GSTG 3

// recurrence smem offsets (bytes)
#define RS_H 0
#define RS_L 65536
#define YSM  131072                 // [2 buf][ hi 16K | lo 16K ]
#define REDO 196608                 // red [8][4][32] floats = 4KB
#define GSMO 200704                 // gsm [32][33] floats = 4224B
#define SMEM_REC (GSMO + 32 * 33 * 4)

// ------------------------- device scratch -------------------------
__device__ float g_gates[(size_t)TT * BB * G4];                 // 256 MB
__device__ unsigned char g_At[(size_t)KCH * MT * GT_A];
__device__ unsigned char g_Bt[(size_t)KCH * NTB * GT_B];
__device__ __nv_bfloat16 g_yh[2][BB * HH];   // y hi, [buf][b][k]
__device__ __nv_bfloat16 g_yl[2][BB * HH];   // y lo
__device__ unsigned g_count;

// ------------------------- helpers -------------------------
__device__ __forceinline__ uint32_t smem_u32(const void* p) {
    uint32_t a;
    asm("{ .reg .u64 t; cvta.to.shared.u64 t, %1; cvt.u32.u64 %0, t; }" : "=r"(a) : "l"(p));
    return a;
}
__device__ __forceinline__ void ldsm4(uint32_t (&r)[4], uint32_t addr) {
    asm volatile("ldmatrix.sync.aligned.m8n8.x4.shared.b16 {%0,%1,%2,%3}, [%4];"
        : "=r"(r[0]), "=r"(r[1]), "=r"(r[2]), "=r"(r[3]) : "r"(addr));
}
__device__ __forceinline__ void mma16816(float (&d)[4], const uint32_t (&a)[4],
                                         uint32_t b0, uint32_t b1) {
    asm volatile("mma.sync.aligned.m16n8k16.row.col.f32.bf16.bf16.f32 "
        "{%0,%1,%2,%3}, {%4,%5,%6,%7}, {%8,%9}, {%0,%1,%2,%3};"
        : "+f"(d[0]), "+f"(d[1]), "+f"(d[2]), "+f"(d[3])
        : "r"(a[0]), "r"(a[1]), "r"(a[2]), "r"(a[3]), "r"(b0), "r"(b1));
}
__device__ __forceinline__ void cp16(uint32_t sdst, const void* gsrc) {
    asm volatile("cp.async.cg.shared.global [%0], [%1], 16;" :: "r"(sdst), "l"(gsrc) : "memory");
}
__device__ __forceinline__ void cp_commit() {
    asm volatile("cp.async.commit_group;" ::: "memory");
}
template<int N> __device__ __forceinline__ void cp_wait() {
    asm volatile("cp.async.wait_group %0;" :: "n"(N) : "memory");
}
__device__ __forceinline__ uint32_t pack_bf2(float a, float b) {
    __nv_bfloat162 h = __floats2bfloat162_rn(a, b);
    return *(uint32_t*)&h;
}
__device__ __forceinline__ float hsig(float v) {
    return __saturatef(v * 0.16666666666666666f + 0.5f);
}
__device__ __forceinline__ float htanh(float v) {
    return fminf(fmaxf(v, -1.f), 1.f);
}

// ------------------------------------------------------------------
// Conversion kernels (unchanged)
// ------------------------------------------------------------------
__global__ __launch_bounds__(256) void convA(const float* __restrict__ x)
{
    int t = blockIdx.x * 256 + threadIdx.x;
    int cg = t & 7;
    int kc = (t >> 3) & 15;
    int m  = t >> 7;

    const float4* xp = (const float4*)(x + (size_t)m * II + kc * 64 + cg * 8);
    float4 v0 = xp[0], v1 = xp[1];
    float f[8] = {v0.x, v0.y, v0.z, v0.w, v1.x, v1.y, v1.z, v1.w};
    float hif[8], lof[8];
#pragma unroll
    for (int i = 0; i < 8; i++) {
        __nv_bfloat16 h = __float2bfloat16_rn(f[i]);
        hif[i] = __bfloat162float(h);
        lof[i] = f[i] - hif[i];
    }
    uint4 hi4 = {pack_bf2(hif[0], hif[1]), pack_bf2(hif[2], hif[3]),
                 pack_bf2(hif[4], hif[5]), pack_bf2(hif[6], hif[7])};
    uint4 lo4 = {pack_bf2(lof[0], lof[1]), pack_bf2(lof[2], lof[3]),
                 pack_bf2(lof[4], lof[5]), pack_bf2(lof[6], lof[7])};

    int mt = m >> 7, r = m & 127;
    uint32_t off = (uint32_t)r * 128 + cg * 16;
    uint32_t sw  = off ^ ((off >> 3) & 0x70);

    *(uint4*)(g_At + ((size_t)(kc +  0) * MT + mt) * GT_A + sw) = hi4;
    *(uint4*)(g_At + ((size_t)(kc + 16) * MT + mt) * GT_A + sw) = hi4;
    *(uint4*)(g_At + ((size_t)(kc + 32) * MT + mt) * GT_A + sw) = lo4;
}

__global__ __launch_bounds__(256) void convB(const float* __restrict__ W)
{
    int t = blockIdx.x * 256 + threadIdx.x;
    int cg = t & 7;
    int kc = (t >> 3) & 15;
    int n  = t >> 7;

    const float4* wp = (const float4*)(W + (size_t)n * II + kc * 64 + cg * 8);
    float4 v0 = wp[0], v1 = wp[1];
    float f[8] = {v0.x, v0.y, v0.z, v0.w, v1.x, v1.y, v1.z, v1.w};
    float hif[8], lof[8];
#pragma unroll
    for (int i = 0; i < 8; i++) {
        __nv_bfloat16 h = __float2bfloat16_rn(f[i]);
        hif[i] = __bfloat162float(h);
        lof[i] = f[i] - hif[i];
    }
    uint4 hi4 = {pack_bf2(hif[0], hif[1]), pack_bf2(hif[2], hif[3]),
                 pack_bf2(hif[4], hif[5]), pack_bf2(hif[6], hif[7])};
    uint4 lo4 = {pack_bf2(lof[0], lof[1]), pack_bf2(lof[2], lof[3]),
                 pack_bf2(lof[4], lof[5]), pack_bf2(lof[6], lof[7])};

    int nt = n >> 7, r = n & 127;
    uint32_t off = (uint32_t)r * 128 + cg * 16;
    uint32_t sw  = off ^ ((off >> 3) & 0x70);

    *(uint4*)(g_Bt + ((size_t)(kc +  0) * NTB + nt) * GT_B + sw) = hi4;
    *(uint4*)(g_Bt + ((size_t)(kc + 16) * NTB + nt) * GT_B + sw) = lo4;
    *(uint4*)(g_Bt + ((size_t)(kc + 32) * NTB + nt) * GT_B + sw) = hi4;
}

// ------------------------------------------------------------------
// HMMA pre-GEMM, CTA tile 256x128. Grid: x = nt, y = mt2 (0..63).
// Stage: A = 2 consecutive 16KB blobs (32KB), B = 16KB.
// 8 warps: wm = warp&3 (64 m rows), wn = warp>>2 (64 n rows).
// ------------------------------------------------------------------
__device__ __forceinline__ void load_stage2(uint32_t sbase, int s, int c, int mt2, int nt, int tid)
{
    uint32_t smA = sbase + s * GST2;
    uint32_t smB = smA + 32768;
    const unsigned char* gA = g_At + ((size_t)c * MT + mt2 * 2) * GT_A;   // 32KB contiguous
    const unsigned char* gB = g_Bt + ((size_t)c * NTB + nt) * GT_B;
#pragma unroll
    for (int i = 0; i < 8; i++) {
        uint32_t off = (uint32_t)(tid + i * 256) * 16;
        cp16(smA + off, gA + off);
    }
#pragma unroll
    for (int i = 0; i < 4; i++) {
        uint32_t off = (uint32_t)(tid + i * 256) * 16;
        cp16(smB + off, gB + off);
    }
}

__global__ __launch_bounds__(256, 1) void gemm_mma(const float* __restrict__ bW,
                                                   const float* __restrict__ bR)
{
    extern __shared__ __align__(128) unsigned char smg[];
    const uint32_t sbase = smem_u32(smg);

    const int tid  = threadIdx.x;
    const int lane = tid & 31;
    const int warp = tid >> 5;
    const int wm   = warp & 3;        // 64-row m quarter
    const int wn   = warp >> 2;       // 64-row n half
    const int nt   = blockIdx.x;
    const int mt2  = blockIdx.y;

    float acc[4][8][4];
#pragma unroll
    for (int i = 0; i < 4; i++)
#pragma unroll
        for (int j = 0; j < 8; j++)
#pragma unroll
            for (int q = 0; q < 4; q++) acc[i][j][q] = 0.f;

    load_stage2(sbase, 0, 0, mt2, nt, tid); cp_commit();
    load_stage2(sbase, 1, 1, mt2, nt, tid); cp_commit();

    const int rl = lane & 15;
    const int chalf = lane >> 4;

#pragma unroll 1
    for (int c = 0; c < KCH; c++) {
        if (c + 2 < KCH) load_stage2(sbase, (c + 2) % GSTG, c + 2, mt2, nt, tid);
        cp_commit();
        cp_wait<2>();
        __syncthreads();

        const uint32_t smA = sbase + (c % GSTG) * GST2;
        const uint32_t smB = smA + 32768;

#pragma unroll
        for (int ks = 0; ks < 4; ks++) {
            const int kb = ks * 32 + chalf * 16;
            uint32_t a[4][4];
#pragma unroll
            for (int i = 0; i < 4; i++) {
                int row = wm * 64 + i * 16 + rl;          // 0..255
                uint32_t off = (uint32_t)(row & 127) * 128 + kb;
                ldsm4(a[i], smA + ((uint32_t)(row >> 7)) * 16384 + (off ^ ((off >> 3) & 0x70)));
            }
            uint32_t b[4][4];
#pragma unroll
            for (int j = 0; j < 4; j++) {
                uint32_t off = (uint32_t)(wn * 64 + j * 16 + rl) * 128 + kb;
                ldsm4(b[j], smB + (off ^ ((off >> 3) & 0x70)));
            }
#pragma unroll
            for (int i = 0; i < 4; i++)
#pragma unroll
                for (int j = 0; j < 4; j++) {
                    mma16816(acc[i][2 * j + 0], a[i], b[j][0], b[j][2]);
                    mma16816(acc[i][2 * j + 1], a[i], b[j][1], b[j][3]);
                }
        }
        __syncthreads();
    }

    const int m0  = mt2 * 256 + wm * 64 + (lane >> 2);
    const int n0g = nt * 128 + wn * 64;
#pragma unroll
    for (int i = 0; i < 4; i++) {
#pragma unroll
        for (int j = 0; j < 8; j++) {
            int n = n0g + j * 8 + (lane & 3) * 2;
            float bx = bW[n] + bR[n];
            float by = bW[n + 1] + bR[n + 1];
            int r0 = m0 + i * 16;
            float2 o0 = {acc[i][j][0] + bx, acc[i][j][1] + by};
            float2 o1 = {acc[i][j][2] + bx, acc[i][j][3] + by};
            *(float2*)&g_gates[(size_t)r0 * G4 + n] = o0;
            *(float2*)&g_gates[(size_t)(r0 + 8) * G4 + n] = o1;
        }
    }
}

// ------------------------------------------------------------------
// Init: reset counter; y0 -> bf16 hi/lo buffers
// ------------------------------------------------------------------
__global__ __launch_bounds__(256) void init_kernel(const float* __restrict__ y0)
{
    int i = blockIdx.x * 256 + threadIdx.x;   // 0..32767
    if (i == 0) g_count = 0;
    float v = y0[i];
    __nv_bfloat16 h = __float2bfloat16_rn(v);
    g_yh[0][i] = h;
    g_yl[0][i] = __float2bfloat16_rn(v - __bfloat162float(h));
}

// ------------------------------------------------------------------
// Persistent tensor-core recurrence (R5 layout: 256 thr, 8 warps).
// Barrier: syncthreads -> tid0 red.release -> ALL threads ld.acquire poll.
// ------------------------------------------------------------------
extern __shared__ __align__(128) unsigned char smrec[];

__device__ __forceinline__ void issue_y_chunk(uint32_t sbase, int buf, int c,
                                              const __nv_bfloat16* __restrict__ yhg,
                                              const __nv_bfloat16* __restrict__ ylg,
                                              int tid)
{
#pragma unroll
    for (int i = 0; i < 8; i++) {
        int gran = tid + i * 256;              // 0..2047
        int half = gran >> 10;
        int bb   = (gran >> 5) & 31;
        int gi   = gran & 31;
        const __nv_bfloat16* src = (half ? ylg : yhg) + bb * 1024 + c * 256 + gi * 8;
        uint32_t dst = sbase + YSM + buf * 32768 + half * 16384 + bb * 512
                     + (((uint32_t)gi * 16) ^ (((uint32_t)bb & 7) << 4));
        cp16(dst, src);
    }
    cp_commit();
}

__global__ __launch_bounds__(NTH, 1) void lstm_persist(const float* __restrict__ R,
                                                       const float* __restrict__ c0,
                                                       float* __restrict__ yout,
                                                       float* __restrict__ cout)
{
    const int tid = threadIdx.x;
    const int blk = blockIdx.x;
    const uint32_t sbase = smem_u32(smrec);

    // ---- load + split + swizzle R slice into SMEM (once) ----
    for (int i = tid; i < 4096; i += NTH) {
        int rr  = i >> 7;
        int g16 = i & 127;
        int G   = (rr >> 3) * HH + blk * 8 + (rr & 7);
        const float4* p = (const float4*)(R + (size_t)G * HH + g16 * 8);
        float4 v0 = p[0], v1 = p[1];
        float f[8] = {v0.x, v0.y, v0.z, v0.w, v1.x, v1.y, v1.z, v1.w};
        float hif[8], lof[8];
#pragma unroll
        for (int j = 0; j < 8; j++) {
            __nv_bfloat16 h = __float2bfloat16_rn(f[j]);
            hif[j] = __bfloat162float(h);
            lof[j] = f[j] - hif[j];
        }
        uint4 hi4 = {pack_bf2(hif[0], hif[1]), pack_bf2(hif[2], hif[3]),
                     pack_bf2(hif[4], hif[5]), pack_bf2(hif[6], hif[7])};
        uint4 lo4 = {pack_bf2(lof[0], lof[1]), pack_bf2(lof[2], lof[3]),
                     pack_bf2(lof[4], lof[5]), pack_bf2(lof[6], lof[7])};
        uint32_t off = (uint32_t)rr * 2048 + (((uint32_t)g16 * 16) ^ (((uint32_t)rr & 7) << 4));
        *(uint4*)(smrec + RS_H + off) = hi4;
        *(uint4*)(smrec + RS_L + off) = lo4;
    }
    __syncthreads();

    const int lane  = tid & 31;
    const int warp  = tid >> 5;
    const int wm    = warp & 1;
    const int wn    = (warp >> 1) & 1;
    const int wk    = warp >> 2;
    const int chalf = lane >> 4;

    const int b  = tid >> 3;
    const int hl = tid & 7;
    const int h  = blk * 8 + hl;

    float c_val = c0[(size_t)b * HH + h];

    float* red = (float*)(smrec + REDO);
    float* gsm = (float*)(smrec + GSMO);

    const uint32_t arow = (uint32_t)(wm * 16 + (lane & 15));
    const uint32_t nrow = (uint32_t)(wn * 16 + (lane & 15));
    const uint32_t aswz = (arow & 7) << 4;
    const uint32_t nswz = (nrow & 7) << 4;
    const uint32_t rbase_h = sbase + RS_H + nrow * 2048;
    const uint32_t rbase_l = sbase + RS_L + nrow * 2048;

    for (int t = 0; t < TT; t++) {
        const int rbuf = t & 1;
        const __nv_bfloat16* yhg = g_yh[rbuf];
        const __nv_bfloat16* ylg = g_yl[rbuf];

        const float* gp = g_gates + (size_t)t * BB * G4 + (size_t)b * G4 + h;
        float gp0 = gp[0 * HH], gp1 = gp[1 * HH], gp2 = gp[2 * HH], gp3 = gp[3 * HH];

        float acc0[4] = {0.f, 0.f, 0.f, 0.f};
        float acc1[4] = {0.f, 0.f, 0.f, 0.f};

        issue_y_chunk(sbase, 0, 0, yhg, ylg, tid);

#pragma unroll
        for (int c = 0; c < 4; c++) {
            if (c < 3) {
                issue_y_chunk(sbase, (c + 1) & 1, c + 1, yhg, ylg, tid);
                cp_wait<1>();
            } else {
                cp_wait<0>();
            }
            __syncthreads();

            const uint32_t ybh = sbase + YSM + (c & 1) * 32768 + arow * 512;
            const uint32_t ybl = ybh + 16384;
            const uint32_t kcb = (uint32_t)c * 512;

#pragma unroll
            for (int s2 = 0; s2 < 8; s2++) {
                const int s = s2 * 2 + wk;
                const uint32_t aoff = (uint32_t)(s * 32 + chalf * 16);
                const uint32_t koff = kcb + aoff;
                uint32_t ah[4], al[4], bh[4], bl[4];
                ldsm4(ah, ybh + (aoff ^ aswz));
                ldsm4(bh, rbase_h + (koff ^ nswz));
                ldsm4(bl, rbase_l + (koff ^ nswz));
                ldsm4(al, ybl + (aoff ^ aswz));
                mma16816(acc0, ah, bh[0], bh[2]);
                mma16816(acc1, ah, bh[1], bh[3]);
                mma16816(acc0, ah, bl[0], bl[2]);
                mma16816(acc1, ah, bl[1], bl[3]);
                mma16816(acc0, al, bh[0], bh[2]);
                mma16816(acc1, al, bh[1], bh[3]);
            }
            __syncthreads();
        }

        // ---- k-split reduce ----
        if (wk == 1) {
            const int w4 = warp & 3;
#pragma unroll
            for (int j = 0; j < 4; j++) {
                red[((j)     * 4 + w4) * 32 + lane] = acc0[j];
                red[((j + 4) * 4 + w4) * 32 + lane] = acc1[j];
            }
        }
        __syncthreads();
        if (wk == 0) {
            const int w4 = warp & 3;
#pragma unroll
            for (int j = 0; j < 4; j++) {
                acc0[j] += red[((j)     * 4 + w4) * 32 + lane];
                acc1[j] += red[((j + 4) * 4 + w4) * 32 + lane];
            }
            const int mrow = wm * 16 + (lane >> 2);
            const int nb0  = wn * 16 + (lane & 3) * 2;
            gsm[(nb0 + 0) * 33 + mrow] = acc0[0];
            gsm[(nb0 + 1) * 33 + mrow] = acc0[1];
            gsm[(nb0 + 0) * 33 + mrow + 8] = acc0[2];
            gsm[(nb0 + 1) * 33 + mrow + 8] = acc0[3];
            gsm[(nb0 + 8) * 33 + mrow] = acc1[0];
            gsm[(nb0 + 9) * 33 + mrow] = acc1[1];
            gsm[(nb0 + 8) * 33 + mrow + 8] = acc1[2];
            gsm[(nb0 + 9) * 33 + mrow + 8] = acc1[3];
        }
        __syncthreads();

        // ---- gate epilogue (all 256 threads) ----
        {
            float si  = gp0 + gsm[(0 * 8 + hl) * 33 + b];
            float sf  = gp1 + gsm[(1 * 8 + hl) * 33 + b];
            float sz  = gp2 + gsm[(2 * 8 + hl) * 33 + b];
            float so4 = gp3 + gsm[(3 * 8 + hl) * 33 + b];
            float i_ = hsig(si);
            float f_ = hsig(sf);
            float z_ = htanh(sz);
            float o_ = hsig(so4);
            c_val = f_ * c_val + i_ * z_;
            float y_ = o_ * htanh(c_val);

            size_t oidx = (size_t)t * BB * HH + (size_t)b * HH + h;
            yout[oidx] = y_;
            cout[oidx] = c_val;

            __nv_bfloat16 yh = __float2bfloat16_rn(y_);
            g_yh[(t + 1) & 1][b * HH + h] = yh;
            g_yl[(t + 1) & 1][b * HH + h] = __float2bfloat16_rn(y_ - __bfloat162float(yh));
        }

        // ---- grid barrier: release + all-threads acquire-poll ----
        if (t < TT - 1) {
            __syncthreads();                     // all warps' y stores done
            if (tid == 0) {
                asm volatile("red.release.gpu.global.add.u32 [%0], %1;"
                             :: "l"(&g_count), "r"(1u) : "memory");
            }
            const unsigned tgt = (unsigned)(NB * (t + 1));
            unsigned v;
            do {
                asm volatile("ld.acquire.gpu.global.u32 %0, [%1];"
                             : "=r"(v) : "l"(&g_count) : "memory");
            } while (v < tgt);
            // no trailing syncthreads: each warp may proceed to issue cp.async;
            // buffer safety is guaranteed by the pre-release syncthreads.
        }
    }
}

// ------------------------------------------------------------------
extern "C" void kernel_launch(void* const* d_in, const int* in_sizes, int n_in,
                              void* d_out, int out_size)
{
    const float* y0 = (const float*)d_in[0];
    const float* c0 = (const float*)d_in[1];
    const float* x  = (const float*)d_in[2];
    const float* W  = (const float*)d_in[3];
    const float* R  = (const float*)d_in[4];
    const float* bW = (const float*)d_in[5];
    const float* bR = (const float*)d_in[6];

    float* yout = (float*)d_out;
    float* cout = yout + (size_t)TT * BB * HH;

    const int smem_gemm = GSTG * GST2;         // 147456
    cudaFuncSetAttribute(gemm_mma, cudaFuncAttributeMaxDynamicSharedMemorySize, smem_gemm);
    cudaFuncSetAttribute(lstm_persist, cudaFuncAttributeMaxDynamicSharedMemorySize, SMEM_REC);

    convA<<<8192, 256>>>(x);
    convB<<<2048, 256>>>(W);
    init_kernel<<<128, 256>>>(y0);
    gemm_mma<<<dim3(NTB, MT / 2), 256, smem_gemm>>>(bW, bR);
    lstm_persist<<<NB, NTH, SMEM_REC>>>(R, c0, yout, cout);
}

// round 12
// speedup vs baseline: 1.1438x; 1.1264x over previous
#include <cuda_runtime.h>
#include <cuda_bf16.h>
#include <cstdint>

#define TT 512
#define BB 32
#define II 1024
#define HH 1024
#define G4 4096   // 4*H
#define NB 128    // persistent CTAs
#define NTH 256   // threads per CTA (recurrence)

#define KCH 48          // K' chunks of 64 (3*1024/64)
#define MT  128         // A blobs per chunk (16384/128)
#define NTB 32          // B blobs per chunk (4096/128)
#define GT_A 16384
#define GT_B 16384
#define GSTAGE_B (GT_A + GT_B)   // 32768
#define GSTG 3

// recurrence smem offsets (bytes)
#define RS_H 0
#define RS_L 65536
#define YSM  131072                 // [2 buf][ hi 16K | lo 16K ]
#define REDO 196608                 // red [8][4][32] floats = 4KB
#define GSMO 200704                 // gsm [32][33] floats = 4224B
#define SMEM_REC (GSMO + 32 * 33 * 4)

// ------------------------- device scratch -------------------------
__device__ float g_gates[(size_t)TT * BB * G4];                 // 256 MB
__device__ unsigned char g_At[(size_t)KCH * MT * GT_A];
__device__ unsigned char g_Bt[(size_t)KCH * NTB * GT_B];
__device__ __nv_bfloat16 g_yh[2][BB * HH];   // y hi, [buf][b][k]
__device__ __nv_bfloat16 g_yl[2][BB * HH];   // y lo
__device__ unsigned g_count;

// ------------------------- helpers -------------------------
__device__ __forceinline__ uint32_t smem_u32(const void* p) {
    uint32_t a;
    asm("{ .reg .u64 t; cvta.to.shared.u64 t, %1; cvt.u32.u64 %0, t; }" : "=r"(a) : "l"(p));
    return a;
}
__device__ __forceinline__ void ldsm4(uint32_t (&r)[4], uint32_t addr) {
    asm volatile("ldmatrix.sync.aligned.m8n8.x4.shared.b16 {%0,%1,%2,%3}, [%4];"
        : "=r"(r[0]), "=r"(r[1]), "=r"(r[2]), "=r"(r[3]) : "r"(addr));
}
__device__ __forceinline__ void mma16816(float (&d)[4], const uint32_t (&a)[4],
                                         uint32_t b0, uint32_t b1) {
    asm volatile("mma.sync.aligned.m16n8k16.row.col.f32.bf16.bf16.f32 "
        "{%0,%1,%2,%3}, {%4,%5,%6,%7}, {%8,%9}, {%0,%1,%2,%3};"
        : "+f"(d[0]), "+f"(d[1]), "+f"(d[2]), "+f"(d[3])
        : "r"(a[0]), "r"(a[1]), "r"(a[2]), "r"(a[3]), "r"(b0), "r"(b1));
}
__device__ __forceinline__ void cp16(uint32_t sdst, const void* gsrc) {
    asm volatile("cp.async.cg.shared.global [%0], [%1], 16;" :: "r"(sdst), "l"(gsrc) : "memory");
}
__device__ __forceinline__ void cp_commit() {
    asm volatile("cp.async.commit_group;" ::: "memory");
}
template<int N> __device__ __forceinline__ void cp_wait() {
    asm volatile("cp.async.wait_group %0;" :: "n"(N) : "memory");
}
__device__ __forceinline__ uint32_t pack_bf2(float a, float b) {
    __nv_bfloat162 h = __floats2bfloat162_rn(a, b);
    return *(uint32_t*)&h;
}
__device__ __forceinline__ float hsig(float v) {
    return __saturatef(v * 0.16666666666666666f + 0.5f);
}
__device__ __forceinline__ float htanh(float v) {
    return fminf(fmaxf(v, -1.f), 1.f);
}

// ------------------------------------------------------------------
// Conversion kernels (unchanged)
// ------------------------------------------------------------------
__global__ __launch_bounds__(256) void convA(const float* __restrict__ x)
{
    int t = blockIdx.x * 256 + threadIdx.x;
    int cg = t & 7;
    int kc = (t >> 3) & 15;
    int m  = t >> 7;

    const float4* xp = (const float4*)(x + (size_t)m * II + kc * 64 + cg * 8);
    float4 v0 = xp[0], v1 = xp[1];
    float f[8] = {v0.x, v0.y, v0.z, v0.w, v1.x, v1.y, v1.z, v1.w};
    float hif[8], lof[8];
#pragma unroll
    for (int i = 0; i < 8; i++) {
        __nv_bfloat16 h = __float2bfloat16_rn(f[i]);
        hif[i] = __bfloat162float(h);
        lof[i] = f[i] - hif[i];
    }
    uint4 hi4 = {pack_bf2(hif[0], hif[1]), pack_bf2(hif[2], hif[3]),
                 pack_bf2(hif[4], hif[5]), pack_bf2(hif[6], hif[7])};
    uint4 lo4 = {pack_bf2(lof[0], lof[1]), pack_bf2(lof[2], lof[3]),
                 pack_bf2(lof[4], lof[5]), pack_bf2(lof[6], lof[7])};

    int mt = m >> 7, r = m & 127;
    uint32_t off = (uint32_t)r * 128 + cg * 16;
    uint32_t sw  = off ^ ((off >> 3) & 0x70);

    *(uint4*)(g_At + ((size_t)(kc +  0) * MT + mt) * GT_A + sw) = hi4;
    *(uint4*)(g_At + ((size_t)(kc + 16) * MT + mt) * GT_A + sw) = hi4;
    *(uint4*)(g_At + ((size_t)(kc + 32) * MT + mt) * GT_A + sw) = lo4;
}

__global__ __launch_bounds__(256) void convB(const float* __restrict__ W)
{
    int t = blockIdx.x * 256 + threadIdx.x;
    int cg = t & 7;
    int kc = (t >> 3) & 15;
    int n  = t >> 7;

    const float4* wp = (const float4*)(W + (size_t)n * II + kc * 64 + cg * 8);
    float4 v0 = wp[0], v1 = wp[1];
    float f[8] = {v0.x, v0.y, v0.z, v0.w, v1.x, v1.y, v1.z, v1.w};
    float hif[8], lof[8];
#pragma unroll
    for (int i = 0; i < 8; i++) {
        __nv_bfloat16 h = __float2bfloat16_rn(f[i]);
        hif[i] = __bfloat162float(h);
        lof[i] = f[i] - hif[i];
    }
    uint4 hi4 = {pack_bf2(hif[0], hif[1]), pack_bf2(hif[2], hif[3]),
                 pack_bf2(hif[4], hif[5]), pack_bf2(hif[6], hif[7])};
    uint4 lo4 = {pack_bf2(lof[0], lof[1]), pack_bf2(lof[2], lof[3]),
                 pack_bf2(lof[4], lof[5]), pack_bf2(lof[6], lof[7])};

    int nt = n >> 7, r = n & 127;
    uint32_t off = (uint32_t)r * 128 + cg * 16;
    uint32_t sw  = off ^ ((off >> 3) & 0x70);

    *(uint4*)(g_Bt + ((size_t)(kc +  0) * NTB + nt) * GT_B + sw) = hi4;
    *(uint4*)(g_Bt + ((size_t)(kc + 16) * NTB + nt) * GT_B + sw) = lo4;
    *(uint4*)(g_Bt + ((size_t)(kc + 32) * NTB + nt) * GT_B + sw) = hi4;
}

// ------------------------------------------------------------------
// HMMA pre-GEMM. CTA tile 128x128, 4 warps of 64x64.
// Grid: x = nt (fast) -> wave shares A tiles. 2 CTAs/SM.
// ------------------------------------------------------------------
__device__ __forceinline__ void load_stage(uint32_t sbase, int s, int c, int mt, int nt, int tid)
{
    uint32_t smA = sbase + s * GSTAGE_B;
    uint32_t smB = smA + GT_A;
    const unsigned char* gA = g_At + ((size_t)c * MT + mt) * GT_A;
    const unsigned char* gB = g_Bt + ((size_t)c * NTB + nt) * GT_B;
#pragma unroll
    for (int i = 0; i < 8; i++) {
        uint32_t off = (uint32_t)(tid + i * 128) * 16;
        cp16(smA + off, gA + off);
    }
#pragma unroll
    for (int i = 0; i < 8; i++) {
        uint32_t off = (uint32_t)(tid + i * 128) * 16;
        cp16(smB + off, gB + off);
    }
}

__global__ __launch_bounds__(128, 2) void gemm_mma(const float* __restrict__ bW,
                                                   const float* __restrict__ bR)
{
    extern __shared__ __align__(128) unsigned char smg[];
    const uint32_t sbase = smem_u32(smg);

    const int tid  = threadIdx.x;
    const int lane = tid & 31;
    const int warp = tid >> 5;
    const int wm   = warp & 1;        // 64-row m half
    const int wn   = warp >> 1;       // 64-row n half
    const int nt   = blockIdx.x;
    const int mt   = blockIdx.y;

    float acc[4][8][4];
#pragma unroll
    for (int i = 0; i < 4; i++)
#pragma unroll
        for (int j = 0; j < 8; j++)
#pragma unroll
            for (int q = 0; q < 4; q++) acc[i][j][q] = 0.f;

    load_stage(sbase, 0, 0, mt, nt, tid); cp_commit();
    load_stage(sbase, 1, 1, mt, nt, tid); cp_commit();

    const int rl = lane & 15;
    const int chalf = lane >> 4;

#pragma unroll 1
    for (int c = 0; c < KCH; c++) {
        if (c + 2 < KCH) load_stage(sbase, (c + 2) % GSTG, c + 2, mt, nt, tid);
        cp_commit();
        cp_wait<2>();
        __syncthreads();

        const uint32_t smA = sbase + (c % GSTG) * GSTAGE_B;
        const uint32_t smB = smA + GT_A;

#pragma unroll
        for (int ks = 0; ks < 4; ks++) {
            const int kb = ks * 32 + chalf * 16;
            uint32_t a[4][4];
#pragma unroll
            for (int i = 0; i < 4; i++) {
                uint32_t off = (uint32_t)(wm * 64 + i * 16 + rl) * 128 + kb;
                ldsm4(a[i], smA + (off ^ ((off >> 3) & 0x70)));
            }
            uint32_t b[4][4];
#pragma unroll
            for (int j = 0; j < 4; j++) {
                uint32_t off = (uint32_t)(wn * 64 + j * 16 + rl) * 128 + kb;
                ldsm4(b[j], smB + (off ^ ((off >> 3) & 0x70)));
            }
#pragma unroll
            for (int i = 0; i < 4; i++)
#pragma unroll
                for (int j = 0; j < 4; j++) {
                    mma16816(acc[i][2 * j + 0], a[i], b[j][0], b[j][2]);
                    mma16816(acc[i][2 * j + 1], a[i], b[j][1], b[j][3]);
                }
        }
        __syncthreads();
    }

    const int m0  = mt * 128 + wm * 64 + (lane >> 2);
    const int n0g = nt * 128 + wn * 64;
#pragma unroll
    for (int i = 0; i < 4; i++) {
#pragma unroll
        for (int j = 0; j < 8; j++) {
            int n = n0g + j * 8 + (lane & 3) * 2;
            float bx = bW[n] + bR[n];
            float by = bW[n + 1] + bR[n + 1];
            int r0 = m0 + i * 16;
            float2 o0 = {acc[i][j][0] + bx, acc[i][j][1] + by};
            float2 o1 = {acc[i][j][2] + bx, acc[i][j][3] + by};
            *(float2*)&g_gates[(size_t)r0 * G4 + n] = o0;
            *(float2*)&g_gates[(size_t)(r0 + 8) * G4 + n] = o1;
        }
    }
}

// ------------------------------------------------------------------
// Init: reset counter; y0 -> bf16 hi/lo buffers
// ------------------------------------------------------------------
__global__ __launch_bounds__(256) void init_kernel(const float* __restrict__ y0)
{
    int i = blockIdx.x * 256 + threadIdx.x;   // 0..32767
    if (i == 0) g_count = 0;
    float v = y0[i];
    __nv_bfloat16 h = __float2bfloat16_rn(v);
    g_yh[0][i] = h;
    g_yl[0][i] = __float2bfloat16_rn(v - __bfloat162float(h));
}

// ------------------------------------------------------------------
// Persistent tensor-core recurrence — EXACT R5 configuration
// (256 threads / 8 warps, tid0-spin grid barrier).
// ------------------------------------------------------------------
extern __shared__ __align__(128) unsigned char smrec[];

__device__ __forceinline__ void issue_y_chunk(uint32_t sbase, int buf, int c,
                                              const __nv_bfloat16* __restrict__ yhg,
                                              const __nv_bfloat16* __restrict__ ylg,
                                              int tid)
{
#pragma unroll
    for (int i = 0; i < 8; i++) {
        int gran = tid + i * 256;              // 0..2047
        int half = gran >> 10;
        int bb   = (gran >> 5) & 31;
        int gi   = gran & 31;
        const __nv_bfloat16* src = (half ? ylg : yhg) + bb * 1024 + c * 256 + gi * 8;
        uint32_t dst = sbase + YSM + buf * 32768 + half * 16384 + bb * 512
                     + (((uint32_t)gi * 16) ^ (((uint32_t)bb & 7) << 4));
        cp16(dst, src);
    }
    cp_commit();
}

__global__ __launch_bounds__(NTH, 1) void lstm_persist(const float* __restrict__ R,
                                                       const float* __restrict__ c0,
                                                       float* __restrict__ yout,
                                                       float* __restrict__ cout)
{
    const int tid = threadIdx.x;
    const int blk = blockIdx.x;
    const uint32_t sbase = smem_u32(smrec);

    // ---- load + split + swizzle R slice into SMEM (once) ----
    for (int i = tid; i < 4096; i += NTH) {
        int rr  = i >> 7;
        int g16 = i & 127;
        int G   = (rr >> 3) * HH + blk * 8 + (rr & 7);
        const float4* p = (const float4*)(R + (size_t)G * HH + g16 * 8);
        float4 v0 = p[0], v1 = p[1];
        float f[8] = {v0.x, v0.y, v0.z, v0.w, v1.x, v1.y, v1.z, v1.w};
        float hif[8], lof[8];
#pragma unroll
        for (int j = 0; j < 8; j++) {
            __nv_bfloat16 h = __float2bfloat16_rn(f[j]);
            hif[j] = __bfloat162float(h);
            lof[j] = f[j] - hif[j];
        }
        uint4 hi4 = {pack_bf2(hif[0], hif[1]), pack_bf2(hif[2], hif[3]),
                     pack_bf2(hif[4], hif[5]), pack_bf2(hif[6], hif[7])};
        uint4 lo4 = {pack_bf2(lof[0], lof[1]), pack_bf2(lof[2], lof[3]),
                     pack_bf2(lof[4], lof[5]), pack_bf2(lof[6], lof[7])};
        uint32_t off = (uint32_t)rr * 2048 + (((uint32_t)g16 * 16) ^ (((uint32_t)rr & 7) << 4));
        *(uint4*)(smrec + RS_H + off) = hi4;
        *(uint4*)(smrec + RS_L + off) = lo4;
    }
    __syncthreads();

    const int lane  = tid & 31;
    const int warp  = tid >> 5;
    const int wm    = warp & 1;
    const int wn    = (warp >> 1) & 1;
    const int wk    = warp >> 2;
    const int chalf = lane >> 4;

    const int b  = tid >> 3;
    const int hl = tid & 7;
    const int h  = blk * 8 + hl;

    float c_val = c0[(size_t)b * HH + h];

    float* red = (float*)(smrec + REDO);
    float* gsm = (float*)(smrec + GSMO);

    const uint32_t arow = (uint32_t)(wm * 16 + (lane & 15));
    const uint32_t nrow = (uint32_t)(wn * 16 + (lane & 15));
    const uint32_t aswz = (arow & 7) << 4;
    const uint32_t nswz = (nrow & 7) << 4;
    const uint32_t rbase_h = sbase + RS_H + nrow * 2048;
    const uint32_t rbase_l = sbase + RS_L + nrow * 2048;

    for (int t = 0; t < TT; t++) {
        const int rbuf = t & 1;
        const __nv_bfloat16* yhg = g_yh[rbuf];
        const __nv_bfloat16* ylg = g_yl[rbuf];

        const float* gp = g_gates + (size_t)t * BB * G4 + (size_t)b * G4 + h;
        float gp0 = gp[0 * HH], gp1 = gp[1 * HH], gp2 = gp[2 * HH], gp3 = gp[3 * HH];

        float acc0[4] = {0.f, 0.f, 0.f, 0.f};
        float acc1[4] = {0.f, 0.f, 0.f, 0.f};

        issue_y_chunk(sbase, 0, 0, yhg, ylg, tid);

#pragma unroll
        for (int c = 0; c < 4; c++) {
            if (c < 3) {
                issue_y_chunk(sbase, (c + 1) & 1, c + 1, yhg, ylg, tid);
                cp_wait<1>();
            } else {
                cp_wait<0>();
            }
            __syncthreads();

            const uint32_t ybh = sbase + YSM + (c & 1) * 32768 + arow * 512;
            const uint32_t ybl = ybh + 16384;
            const uint32_t kcb = (uint32_t)c * 512;

#pragma unroll
            for (int s2 = 0; s2 < 8; s2++) {
                const int s = s2 * 2 + wk;
                const uint32_t aoff = (uint32_t)(s * 32 + chalf * 16);
                const uint32_t koff = kcb + aoff;
                uint32_t ah[4], al[4], bh[4], bl[4];
                ldsm4(ah, ybh + (aoff ^ aswz));
                ldsm4(bh, rbase_h + (koff ^ nswz));
                ldsm4(bl, rbase_l + (koff ^ nswz));
                ldsm4(al, ybl + (aoff ^ aswz));
                mma16816(acc0, ah, bh[0], bh[2]);
                mma16816(acc1, ah, bh[1], bh[3]);
                mma16816(acc0, ah, bl[0], bl[2]);
                mma16816(acc1, ah, bl[1], bl[3]);
                mma16816(acc0, al, bh[0], bh[2]);
                mma16816(acc1, al, bh[1], bh[3]);
            }
            __syncthreads();
        }

        // ---- k-split reduce ----
        if (wk == 1) {
            const int w4 = warp & 3;
#pragma unroll
            for (int j = 0; j < 4; j++) {
                red[((j)     * 4 + w4) * 32 + lane] = acc0[j];
                red[((j + 4) * 4 + w4) * 32 + lane] = acc1[j];
            }
        }
        __syncthreads();
        if (wk == 0) {
            const int w4 = warp & 3;
#pragma unroll
            for (int j = 0; j < 4; j++) {
                acc0[j] += red[((j)     * 4 + w4) * 32 + lane];
                acc1[j] += red[((j + 4) * 4 + w4) * 32 + lane];
            }
            const int mrow = wm * 16 + (lane >> 2);
            const int nb0  = wn * 16 + (lane & 3) * 2;
            gsm[(nb0 + 0) * 33 + mrow] = acc0[0];
            gsm[(nb0 + 1) * 33 + mrow] = acc0[1];
            gsm[(nb0 + 0) * 33 + mrow + 8] = acc0[2];
            gsm[(nb0 + 1) * 33 + mrow + 8] = acc0[3];
            gsm[(nb0 + 8) * 33 + mrow] = acc1[0];
            gsm[(nb0 + 9) * 33 + mrow] = acc1[1];
            gsm[(nb0 + 8) * 33 + mrow + 8] = acc1[2];
            gsm[(nb0 + 9) * 33 + mrow + 8] = acc1[3];
        }
        __syncthreads();

        // ---- gate epilogue (all 256 threads) ----
        {
            float si  = gp0 + gsm[(0 * 8 + hl) * 33 + b];
            float sf  = gp1 + gsm[(1 * 8 + hl) * 33 + b];
            float sz  = gp2 + gsm[(2 * 8 + hl) * 33 + b];
            float so4 = gp3 + gsm[(3 * 8 + hl) * 33 + b];
            float i_ = hsig(si);
            float f_ = hsig(sf);
            float z_ = htanh(sz);
            float o_ = hsig(so4);
            c_val = f_ * c_val + i_ * z_;
            float y_ = o_ * htanh(c_val);

            size_t oidx = (size_t)t * BB * HH + (size_t)b * HH + h;
            yout[oidx] = y_;
            cout[oidx] = c_val;

            __nv_bfloat16 yh = __float2bfloat16_rn(y_);
            g_yh[(t + 1) & 1][b * HH + h] = yh;
            g_yl[(t + 1) & 1][b * HH + h] = __float2bfloat16_rn(y_ - __bfloat162float(yh));
        }

        // ---- grid barrier (R5 original: tid0 atomic + spin) ----
        if (t < TT - 1) {
            __syncthreads();
            if (tid == 0) {
                __threadfence();
                atomicAdd(&g_count, 1u);
                unsigned tgt = (unsigned)(NB * (t + 1));
                while (*((volatile unsigned*)&g_count) < tgt) { }
                __threadfence();
            }
            __syncthreads();
        }
    }
}

// ------------------------------------------------------------------
extern "C" void kernel_launch(void* const* d_in, const int* in_sizes, int n_in,
                              void* d_out, int out_size)
{
    const float* y0 = (const float*)d_in[0];
    const float* c0 = (const float*)d_in[1];
    const float* x  = (const float*)d_in[2];
    const float* W  = (const float*)d_in[3];
    const float* R  = (const float*)d_in[4];
    const float* bW = (const float*)d_in[5];
    const float* bR = (const float*)d_in[6];

    float* yout = (float*)d_out;
    float* cout = yout + (size_t)TT * BB * HH;

    const int smem_gemm = GSTG * GSTAGE_B;     // 98304
    cudaFuncSetAttribute(gemm_mma, cudaFuncAttributeMaxDynamicSharedMemorySize, smem_gemm);
    cudaFuncSetAttribute(lstm_persist, cudaFuncAttributeMaxDynamicSharedMemorySize, SMEM_REC);

    convA<<<8192, 256>>>(x);
    convB<<<2048, 256>>>(W);
    init_kernel<<<128, 256>>>(y0);
    gemm_mma<<<dim3(NTB, MT), 128, smem_gemm>>>(bW, bR);
    lstm_persist<<<NB, NTH, SMEM_REC>>>(R, c0, yout, cout);
}

// round 14
// speedup vs baseline: 1.2221x; 1.0684x over previous
#include <cuda_runtime.h>
#include <cuda_bf16.h>
#include <cuda_fp16.h>
#include <cstdint>

#define TT 512
#define BB 32
#define II 1024
#define HH 1024
#define G4 4096   // 4*H
#define NB 128    // persistent CTAs
#define NTH 256   // threads per CTA (recurrence)

#define KCH 48          // K' chunks of 64 (3*1024/64)
#define MT  128         // A blobs per chunk (16384/128)
#define NTB 32          // B blobs per chunk (4096/128)
#define GT_A 16384
#define GT_B 16384
#define GSTAGE_B (GT_A + GT_B)   // 32768
#define GSTG 3

// recurrence smem offsets (bytes)
#define RS_H 0                      // R hi fp16: 32 rows x 1024 k = 64KB
#define RS_L 65536                  // R lo fp16: 64KB
#define YSM  131072                 // y hi fp16: 2 buf x 16KB
#define YBUF 16384
#define GSM  163840                 // 4 arrays of [32][33] floats (4224B each)
#define SMEM_REC (GSM + 4 * 4224)

// ------------------------- device scratch -------------------------
__device__ float g_gates[(size_t)TT * BB * G4];                 // 256 MB
__device__ unsigned char g_At[(size_t)KCH * MT * GT_A];
__device__ unsigned char g_Bt[(size_t)KCH * NTB * GT_B];
__device__ __half g_y16[2][BB * HH];         // y fp16, [buf][b][k]
__device__ unsigned g_count;

// ------------------------- helpers -------------------------
__device__ __forceinline__ uint32_t smem_u32(const void* p) {
    uint32_t a;
    asm("{ .reg .u64 t; cvta.to.shared.u64 t, %1; cvt.u32.u64 %0, t; }" : "=r"(a) : "l"(p));
    return a;
}
__device__ __forceinline__ void ldsm4(uint32_t (&r)[4], uint32_t addr) {
    asm volatile("ldmatrix.sync.aligned.m8n8.x4.shared.b16 {%0,%1,%2,%3}, [%4];"
        : "=r"(r[0]), "=r"(r[1]), "=r"(r[2]), "=r"(r[3]) : "r"(addr));
}
__device__ __forceinline__ void mma16816(float (&d)[4], const uint32_t (&a)[4],
                                         uint32_t b0, uint32_t b1) {
    asm volatile("mma.sync.aligned.m16n8k16.row.col.f32.bf16.bf16.f32 "
        "{%0,%1,%2,%3}, {%4,%5,%6,%7}, {%8,%9}, {%0,%1,%2,%3};"
        : "+f"(d[0]), "+f"(d[1]), "+f"(d[2]), "+f"(d[3])
        : "r"(a[0]), "r"(a[1]), "r"(a[2]), "r"(a[3]), "r"(b0), "r"(b1));
}
__device__ __forceinline__ void mma16816h(float (&d)[4], const uint32_t (&a)[4],
                                          uint32_t b0, uint32_t b1) {
    asm volatile("mma.sync.aligned.m16n8k16.row.col.f32.f16.f16.f32 "
        "{%0,%1,%2,%3}, {%4,%5,%6,%7}, {%8,%9}, {%0,%1,%2,%3};"
        : "+f"(d[0]), "+f"(d[1]), "+f"(d[2]), "+f"(d[3])
        : "r"(a[0]), "r"(a[1]), "r"(a[2]), "r"(a[3]), "r"(b0), "r"(b1));
}
__device__ __forceinline__ void cp16(uint32_t sdst, const void* gsrc) {
    asm volatile("cp.async.cg.shared.global [%0], [%1], 16;" :: "r"(sdst), "l"(gsrc) : "memory");
}
__device__ __forceinline__ void cp_commit() {
    asm volatile("cp.async.commit_group;" ::: "memory");
}
template<int N> __device__ __forceinline__ void cp_wait() {
    asm volatile("cp.async.wait_group %0;" :: "n"(N) : "memory");
}
__device__ __forceinline__ uint32_t pack_bf2(float a, float b) {
    __nv_bfloat162 h = __floats2bfloat162_rn(a, b);
    return *(uint32_t*)&h;
}
__device__ __forceinline__ uint32_t pack_h2(float a, float b) {
    __half2 h = __floats2half2_rn(a, b);
    return *(uint32_t*)&h;
}
__device__ __forceinline__ float hsig(float v) {
    return __saturatef(v * 0.16666666666666666f + 0.5f);
}
__device__ __forceinline__ float htanh(float v) {
    return fminf(fmaxf(v, -1.f), 1.f);
}

// ------------------------------------------------------------------
// Conversion kernels (unchanged)
// ------------------------------------------------------------------
__global__ __launch_bounds__(256) void convA(const float* __restrict__ x)
{
    int t = blockIdx.x * 256 + threadIdx.x;
    int cg = t & 7;
    int kc = (t >> 3) & 15;
    int m  = t >> 7;

    const float4* xp = (const float4*)(x + (size_t)m * II + kc * 64 + cg * 8);
    float4 v0 = xp[0], v1 = xp[1];
    float f[8] = {v0.x, v0.y, v0.z, v0.w, v1.x, v1.y, v1.z, v1.w};
    float hif[8], lof[8];
#pragma unroll
    for (int i = 0; i < 8; i++) {
        __nv_bfloat16 h = __float2bfloat16_rn(f[i]);
        hif[i] = __bfloat162float(h);
        lof[i] = f[i] - hif[i];
    }
    uint4 hi4 = {pack_bf2(hif[0], hif[1]), pack_bf2(hif[2], hif[3]),
                 pack_bf2(hif[4], hif[5]), pack_bf2(hif[6], hif[7])};
    uint4 lo4 = {pack_bf2(lof[0], lof[1]), pack_bf2(lof[2], lof[3]),
                 pack_bf2(lof[4], lof[5]), pack_bf2(lof[6], lof[7])};

    int mt = m >> 7, r = m & 127;
    uint32_t off = (uint32_t)r * 128 + cg * 16;
    uint32_t sw  = off ^ ((off >> 3) & 0x70);

    *(uint4*)(g_At + ((size_t)(kc +  0) * MT + mt) * GT_A + sw) = hi4;
    *(uint4*)(g_At + ((size_t)(kc + 16) * MT + mt) * GT_A + sw) = hi4;
    *(uint4*)(g_At + ((size_t)(kc + 32) * MT + mt) * GT_A + sw) = lo4;
}

__global__ __launch_bounds__(256) void convB(const float* __restrict__ W)
{
    int t = blockIdx.x * 256 + threadIdx.x;
    int cg = t & 7;
    int kc = (t >> 3) & 15;
    int n  = t >> 7;

    const float4* wp = (const float4*)(W + (size_t)n * II + kc * 64 + cg * 8);
    float4 v0 = wp[0], v1 = wp[1];
    float f[8] = {v0.x, v0.y, v0.z, v0.w, v1.x, v1.y, v1.z, v1.w};
    float hif[8], lof[8];
#pragma unroll
    for (int i = 0; i < 8; i++) {
        __nv_bfloat16 h = __float2bfloat16_rn(f[i]);
        hif[i] = __bfloat162float(h);
        lof[i] = f[i] - hif[i];
    }
    uint4 hi4 = {pack_bf2(hif[0], hif[1]), pack_bf2(hif[2], hif[3]),
                 pack_bf2(hif[4], hif[5]), pack_bf2(hif[6], hif[7])};
    uint4 lo4 = {pack_bf2(lof[0], lof[1]), pack_bf2(lof[2], lof[3]),
                 pack_bf2(lof[4], lof[5]), pack_bf2(lof[6], lof[7])};

    int nt = n >> 7, r = n & 127;
    uint32_t off = (uint32_t)r * 128 + cg * 16;
    uint32_t sw  = off ^ ((off >> 3) & 0x70);

    *(uint4*)(g_Bt + ((size_t)(kc +  0) * NTB + nt) * GT_B + sw) = hi4;
    *(uint4*)(g_Bt + ((size_t)(kc + 16) * NTB + nt) * GT_B + sw) = lo4;
    *(uint4*)(g_Bt + ((size_t)(kc + 32) * NTB + nt) * GT_B + sw) = hi4;
}

// ------------------------------------------------------------------
// HMMA pre-GEMM (R12 winner: 128x128 CTA, 4 warps of 64x64, 2 CTA/SM)
// ------------------------------------------------------------------
__device__ __forceinline__ void load_stage(uint32_t sbase, int s, int c, int mt, int nt, int tid)
{
    uint32_t smA = sbase + s * GSTAGE_B;
    uint32_t smB = smA + GT_A;
    const unsigned char* gA = g_At + ((size_t)c * MT + mt) * GT_A;
    const unsigned char* gB = g_Bt + ((size_t)c * NTB + nt) * GT_B;
#pragma unroll
    for (int i = 0; i < 8; i++) {
        uint32_t off = (uint32_t)(tid + i * 128) * 16;
        cp16(smA + off, gA + off);
    }
#pragma unroll
    for (int i = 0; i < 8; i++) {
        uint32_t off = (uint32_t)(tid + i * 128) * 16;
        cp16(smB + off, gB + off);
    }
}

__global__ __launch_bounds__(128, 2) void gemm_mma(const float* __restrict__ bW,
                                                   const float* __restrict__ bR)
{
    extern __shared__ __align__(128) unsigned char smg[];
    const uint32_t sbase = smem_u32(smg);

    const int tid  = threadIdx.x;
    const int lane = tid & 31;
    const int warp = tid >> 5;
    const int wm   = warp & 1;
    const int wn   = warp >> 1;
    const int nt   = blockIdx.x;
    const int mt   = blockIdx.y;

    float acc[4][8][4];
#pragma unroll
    for (int i = 0; i < 4; i++)
#pragma unroll
        for (int j = 0; j < 8; j++)
#pragma unroll
            for (int q = 0; q < 4; q++) acc[i][j][q] = 0.f;

    load_stage(sbase, 0, 0, mt, nt, tid); cp_commit();
    load_stage(sbase, 1, 1, mt, nt, tid); cp_commit();

    const int rl = lane & 15;
    const int chalf = lane >> 4;

#pragma unroll 1
    for (int c = 0; c < KCH; c++) {
        if (c + 2 < KCH) load_stage(sbase, (c + 2) % GSTG, c + 2, mt, nt, tid);
        cp_commit();
        cp_wait<2>();
        __syncthreads();

        const uint32_t smA = sbase + (c % GSTG) * GSTAGE_B;
        const uint32_t smB = smA + GT_A;

#pragma unroll
        for (int ks = 0; ks < 4; ks++) {
            const int kb = ks * 32 + chalf * 16;
            uint32_t a[4][4];
#pragma unroll
            for (int i = 0; i < 4; i++) {
                uint32_t off = (uint32_t)(wm * 64 + i * 16 + rl) * 128 + kb;
                ldsm4(a[i], smA + (off ^ ((off >> 3) & 0x70)));
            }
            uint32_t b[4][4];
#pragma unroll
            for (int j = 0; j < 4; j++) {
                uint32_t off = (uint32_t)(wn * 64 + j * 16 + rl) * 128 + kb;
                ldsm4(b[j], smB + (off ^ ((off >> 3) & 0x70)));
            }
#pragma unroll
            for (int i = 0; i < 4; i++)
#pragma unroll
                for (int j = 0; j < 4; j++) {
                    mma16816(acc[i][2 * j + 0], a[i], b[j][0], b[j][2]);
                    mma16816(acc[i][2 * j + 1], a[i], b[j][1], b[j][3]);
                }
        }
        __syncthreads();
    }

    const int m0  = mt * 128 + wm * 64 + (lane >> 2);
    const int n0g = nt * 128 + wn * 64;
#pragma unroll
    for (int i = 0; i < 4; i++) {
#pragma unroll
        for (int j = 0; j < 8; j++) {
            int n = n0g + j * 8 + (lane & 3) * 2;
            float bx = bW[n] + bR[n];
            float by = bW[n + 1] + bR[n + 1];
            int r0 = m0 + i * 16;
            float2 o0 = {acc[i][j][0] + bx, acc[i][j][1] + by};
            float2 o1 = {acc[i][j][2] + bx, acc[i][j][3] + by};
            *(float2*)&g_gates[(size_t)r0 * G4 + n] = o0;
            *(float2*)&g_gates[(size_t)(r0 + 8) * G4 + n] = o1;
        }
    }
}

// ------------------------------------------------------------------
// Init: reset counter; y0 -> fp16 buffer
// ------------------------------------------------------------------
__global__ __launch_bounds__(256) void init_kernel(const float* __restrict__ y0)
{
    int i = blockIdx.x * 256 + threadIdx.x;   // 0..32767
    if (i == 0) g_count = 0;
    g_y16[0][i] = __float2half_rn(y0[i]);
}

// ------------------------------------------------------------------
// Persistent tensor-core recurrence, fp16 2-term (yh*(Rh+Rl)).
// 256 threads / 8 warps: wn = warp&1 (16 n rows), wk = warp>>1 (k quarter).
// Each warp: m32 x n16 x 64k per chunk. 4 gsm partials, 1 reduce sync.
// ------------------------------------------------------------------
extern __shared__ __align__(128) unsigned char smrec[];

__device__ __forceinline__ void issue_y_chunk(uint32_t sbase, int buf, int c,
                                              const __half* __restrict__ yg,
                                              int tid)
{
#pragma unroll
    for (int i = 0; i < 4; i++) {
        int gran = tid + i * 256;              // 0..1023
        int bb   = gran >> 5;
        int gi   = gran & 31;
        const __half* src = yg + bb * 1024 + c * 256 + gi * 8;
        uint32_t dst = sbase + YSM + buf * YBUF + bb * 512
                     + (((uint32_t)gi * 16) ^ (((uint32_t)bb & 7) << 4));
        cp16(dst, src);
    }
    cp_commit();
}

__global__ __launch_bounds__(NTH, 1) void lstm_persist(const float* __restrict__ R,
                                                       const float* __restrict__ c0,
                                                       float* __restrict__ yout,
                                                       float* __restrict__ cout)
{
    const int tid = threadIdx.x;
    const int blk = blockIdx.x;
    const uint32_t sbase = smem_u32(smrec);

    // ---- load + split + swizzle R slice into SMEM as fp16 hi/lo (once) ----
    for (int i = tid; i < 4096; i += NTH) {        // 32 rows x 128 granules(8 fp16)
        int rr  = i >> 7;
        int g16 = i & 127;
        int G   = (rr >> 3) * HH + blk * 8 + (rr & 7);
        const float4* p = (const float4*)(R + (size_t)G * HH + g16 * 8);
        float4 v0 = p[0], v1 = p[1];
        float f[8] = {v0.x, v0.y, v0.z, v0.w, v1.x, v1.y, v1.z, v1.w};
        float hif[8], lof[8];
#pragma unroll
        for (int j = 0; j < 8; j++) {
            __half h = __float2half_rn(f[j]);
            hif[j] = __half2float(h);
            lof[j] = f[j] - hif[j];
        }
        uint4 hi4 = {pack_h2(hif[0], hif[1]), pack_h2(hif[2], hif[3]),
                     pack_h2(hif[4], hif[5]), pack_h2(hif[6], hif[7])};
        uint4 lo4 = {pack_h2(lof[0], lof[1]), pack_h2(lof[2], lof[3]),
                     pack_h2(lof[4], lof[5]), pack_h2(lof[6], lof[7])};
        uint32_t off = (uint32_t)rr * 2048 + (((uint32_t)g16 * 16) ^ (((uint32_t)rr & 7) << 4));
        *(uint4*)(smrec + RS_H + off) = hi4;
        *(uint4*)(smrec + RS_L + off) = lo4;
    }
    __syncthreads();

    const int lane  = tid & 31;
    const int warp  = tid >> 5;
    const int wn    = warp & 1;        // n half (16 rows)
    const int wk    = warp >> 1;       // k quarter
    const int l15   = lane & 15;
    const int chalf = lane >> 4;

    const int b  = tid >> 3;
    const int hl = tid & 7;
    const int h  = blk * 8 + hl;

    float c_val = c0[(size_t)b * HH + h];

    // A (y) fragment addressing: rows l15 and 16+l15 (m32 per warp)
    const uint32_t aswz = (uint32_t)(l15 & 7) << 4;
    // B (R) fragment addressing
    const uint32_t nrow = (uint32_t)(wn * 16 + l15);
    const uint32_t nswz = (nrow & 7) << 4;
    const uint32_t rbh  = sbase + RS_H + nrow * 2048;
    const uint32_t rbl  = sbase + RS_L + nrow * 2048;

    for (int t = 0; t < TT; t++) {
        const int rbuf = t & 1;
        const __half* yg = g_y16[rbuf];

        const float* gp = g_gates + (size_t)t * BB * G4 + (size_t)b * G4 + h;
        float gp0 = gp[0 * HH], gp1 = gp[1 * HH], gp2 = gp[2 * HH], gp3 = gp[3 * HH];

        float acc00[4] = {0.f, 0.f, 0.f, 0.f};
        float acc01[4] = {0.f, 0.f, 0.f, 0.f};
        float acc10[4] = {0.f, 0.f, 0.f, 0.f};
        float acc11[4] = {0.f, 0.f, 0.f, 0.f};

        issue_y_chunk(sbase, 0, 0, yg, tid);

#pragma unroll
        for (int c = 0; c < 4; c++) {
            cp_wait<0>();
            __syncthreads();
            if (c < 3) issue_y_chunk(sbase, (c + 1) & 1, c + 1, yg, tid);

            const uint32_t yb = sbase + YSM + (c & 1) * YBUF;
            const uint32_t a0b = yb + (uint32_t)l15 * 512;
            const uint32_t a1b = yb + (uint32_t)(16 + l15) * 512;

#pragma unroll
            for (int s = 0; s < 4; s++) {
                const uint32_t sa   = (uint32_t)(wk * 4 + s);
                const uint32_t aoff = sa * 32 + chalf * 16;
                const uint32_t koff = (uint32_t)c * 512 + aoff;
                uint32_t a0[4], a1[4], bh[4], bl[4];
                ldsm4(a0, a0b + (aoff ^ aswz));
                ldsm4(a1, a1b + (aoff ^ aswz));
                ldsm4(bh, rbh + (koff ^ nswz));
                ldsm4(bl, rbl + (koff ^ nswz));
                mma16816h(acc00, a0, bh[0], bh[2]);
                mma16816h(acc01, a0, bh[1], bh[3]);
                mma16816h(acc10, a1, bh[0], bh[2]);
                mma16816h(acc11, a1, bh[1], bh[3]);
                mma16816h(acc00, a0, bl[0], bl[2]);
                mma16816h(acc01, a0, bl[1], bl[3]);
                mma16816h(acc10, a1, bl[0], bl[2]);
                mma16816h(acc11, a1, bl[1], bl[3]);
            }
        }

        // ---- per-warp partial write (4 gsm arrays, by wk) ----
        {
            float* gsmk = (float*)(smrec + GSM + wk * 4224);
            const int mrow = lane >> 2;
            const int nb0  = wn * 16 + (lane & 3) * 2;
            gsmk[(nb0 + 0) * 33 + mrow]      = acc00[0];
            gsmk[(nb0 + 1) * 33 + mrow]      = acc00[1];
            gsmk[(nb0 + 0) * 33 + mrow + 8]  = acc00[2];
            gsmk[(nb0 + 1) * 33 + mrow + 8]  = acc00[3];
            gsmk[(nb0 + 8) * 33 + mrow]      = acc01[0];
            gsmk[(nb0 + 9) * 33 + mrow]      = acc01[1];
            gsmk[(nb0 + 8) * 33 + mrow + 8]  = acc01[2];
            gsmk[(nb0 + 9) * 33 + mrow + 8]  = acc01[3];
            gsmk[(nb0 + 0) * 33 + mrow + 16] = acc10[0];
            gsmk[(nb0 + 1) * 33 + mrow + 16] = acc10[1];
            gsmk[(nb0 + 0) * 33 + mrow + 24] = acc10[2];
            gsmk[(nb0 + 1) * 33 + mrow + 24] = acc10[3];
            gsmk[(nb0 + 8) * 33 + mrow + 16] = acc11[0];
            gsmk[(nb0 + 9) * 33 + mrow + 16] = acc11[1];
            gsmk[(nb0 + 8) * 33 + mrow + 24] = acc11[2];
            gsmk[(nb0 + 9) * 33 + mrow + 24] = acc11[3];
        }
        __syncthreads();

        // ---- gate epilogue (all 256 threads) ----
        {
            float si = gp0, sf = gp1, sz = gp2, so4 = gp3;
#pragma unroll
            for (int q = 0; q < 4; q++) {
                const float* gq = (const float*)(smrec + GSM + q * 4224);
                si  += gq[(0 * 8 + hl) * 33 + b];
                sf  += gq[(1 * 8 + hl) * 33 + b];
                sz  += gq[(2 * 8 + hl) * 33 + b];
                so4 += gq[(3 * 8 + hl) * 33 + b];
            }
            float i_ = hsig(si);
            float f_ = hsig(sf);
            float z_ = htanh(sz);
            float o_ = hsig(so4);
            c_val = f_ * c_val + i_ * z_;
            float y_ = o_ * htanh(c_val);

            size_t oidx = (size_t)t * BB * HH + (size_t)b * HH + h;
            yout[oidx] = y_;
            cout[oidx] = c_val;

            g_y16[(t + 1) & 1][b * HH + h] = __float2half_rn(y_);
        }

        // ---- grid barrier (tid0 atomic + spin) ----
        if (t < TT - 1) {
            __syncthreads();
            if (tid == 0) {
                __threadfence();
                atomicAdd(&g_count, 1u);
                unsigned tgt = (unsigned)(NB * (t + 1));
                while (*((volatile unsigned*)&g_count) < tgt) { }
                __threadfence();
            }
            __syncthreads();
        }
    }
}

// ------------------------------------------------------------------
extern "C" void kernel_launch(void* const* d_in, const int* in_sizes, int n_in,
                              void* d_out, int out_size)
{
    const float* y0 = (const float*)d_in[0];
    const float* c0 = (const float*)d_in[1];
    const float* x  = (const float*)d_in[2];
    const float* W  = (const float*)d_in[3];
    const float* R  = (const float*)d_in[4];
    const float* bW = (const float*)d_in[5];
    const float* bR = (const float*)d_in[6];

    float* yout = (float*)d_out;
    float* cout = yout + (size_t)TT * BB * HH;

    const int smem_gemm = GSTG * GSTAGE_B;     // 98304
    cudaFuncSetAttribute(gemm_mma, cudaFuncAttributeMaxDynamicSharedMemorySize, smem_gemm);
    cudaFuncSetAttribute(lstm_persist, cudaFuncAttributeMaxDynamicSharedMemorySize, SMEM_REC);

    convA<<<8192, 256>>>(x);
    convB<<<2048, 256>>>(W);
    init_kernel<<<128, 256>>>(y0);
    gemm_mma<<<dim3(NTB, MT), 128, smem_gemm>>>(bW, bR);
    lstm_persist<<<NB, NTH, SMEM_REC>>>(R, c0, yout, cout);
}

// round 16
// speedup vs baseline: 1.4059x; 1.1504x over previous
#include <cuda_runtime.h>
#include <cuda_bf16.h>
#include <cuda_fp16.h>
#include <cstdint>

#define TT 512
#define BB 32
#define II 1024
#define HH 1024
#define G4 4096   // 4*H
#define NB 128    // persistent CTAs
#define NTH 256   // threads per CTA (recurrence)

#define KCHG 32         // gemm K' chunks of 64 (2*1024/64), fp16 2-term
#define MT  128         // A blobs per chunk (16384/128)
#define NTB 32          // B blobs per chunk (4096/128)
#define GT_A 16384
#define GT_B 16384
#define GSTAGE_B (GT_A + GT_B)   // 32768
#define GSTG 3

// recurrence smem offsets (bytes)
#define RS_H 0                      // R hi fp16: 32 rows x 1024 k = 64KB
#define RS_L 65536                  // R lo fp16: 64KB
#define YSM  131072                 // y fp16: 2 buf x 16KB
#define YBUF 16384
#define GSM  163840                 // 4 arrays of [32][33] floats (4224B each)
#define SMEM_REC (GSM + 4 * 4224)

// ------------------------- device scratch -------------------------
__device__ float g_gates[(size_t)TT * BB * G4];                 // 256 MB
__device__ unsigned char g_At[(size_t)KCHG * MT * GT_A];        // 64 MB
__device__ unsigned char g_Bt[(size_t)KCHG * NTB * GT_B];       // 16 MB
__device__ __half g_y16[2][BB * HH];         // y fp16, [buf][b][k]
__device__ unsigned g_cnt[16 * 32];          // 16 counters, 128B apart

// ------------------------- helpers -------------------------
__device__ __forceinline__ uint32_t smem_u32(const void* p) {
    uint32_t a;
    asm("{ .reg .u64 t; cvta.to.shared.u64 t, %1; cvt.u32.u64 %0, t; }" : "=r"(a) : "l"(p));
    return a;
}
__device__ __forceinline__ void ldsm4(uint32_t (&r)[4], uint32_t addr) {
    asm volatile("ldmatrix.sync.aligned.m8n8.x4.shared.b16 {%0,%1,%2,%3}, [%4];"
        : "=r"(r[0]), "=r"(r[1]), "=r"(r[2]), "=r"(r[3]) : "r"(addr));
}
__device__ __forceinline__ void mma16816h(float (&d)[4], const uint32_t (&a)[4],
                                          uint32_t b0, uint32_t b1) {
    asm volatile("mma.sync.aligned.m16n8k16.row.col.f32.f16.f16.f32 "
        "{%0,%1,%2,%3}, {%4,%5,%6,%7}, {%8,%9}, {%0,%1,%2,%3};"
        : "+f"(d[0]), "+f"(d[1]), "+f"(d[2]), "+f"(d[3])
        : "r"(a[0]), "r"(a[1]), "r"(a[2]), "r"(a[3]), "r"(b0), "r"(b1));
}
__device__ __forceinline__ void cp16(uint32_t sdst, const void* gsrc) {
    asm volatile("cp.async.cg.shared.global [%0], [%1], 16;" :: "r"(sdst), "l"(gsrc) : "memory");
}
__device__ __forceinline__ void cp_commit() {
    asm volatile("cp.async.commit_group;" ::: "memory");
}
template<int N> __device__ __forceinline__ void cp_wait() {
    asm volatile("cp.async.wait_group %0;" :: "n"(N) : "memory");
}
__device__ __forceinline__ uint32_t pack_h2(float a, float b) {
    __half2 h = __floats2half2_rn(a, b);
    return *(uint32_t*)&h;
}
__device__ __forceinline__ float hsig(float v) {
    return __saturatef(v * 0.16666666666666666f + 0.5f);
}
__device__ __forceinline__ float htanh(float v) {
    return fminf(fmaxf(v, -1.f), 1.f);
}

// ------------------------------------------------------------------
// Conversion: x -> A' = [x_h | x_h] fp16 tiles (128x64), SW128 swizzle
// ------------------------------------------------------------------
__global__ __launch_bounds__(256) void convA(const float* __restrict__ x)
{
    int t = blockIdx.x * 256 + threadIdx.x;
    int cg = t & 7;
    int kc = (t >> 3) & 15;
    int m  = t >> 7;

    const float4* xp = (const float4*)(x + (size_t)m * II + kc * 64 + cg * 8);
    float4 v0 = xp[0], v1 = xp[1];
    float f[8] = {v0.x, v0.y, v0.z, v0.w, v1.x, v1.y, v1.z, v1.w};
    uint4 hi4 = {pack_h2(f[0], f[1]), pack_h2(f[2], f[3]),
                 pack_h2(f[4], f[5]), pack_h2(f[6], f[7])};

    int mt = m >> 7, r = m & 127;
    uint32_t off = (uint32_t)r * 128 + cg * 16;
    uint32_t sw  = off ^ ((off >> 3) & 0x70);

    *(uint4*)(g_At + ((size_t)(kc +  0) * MT + mt) * GT_A + sw) = hi4;
    *(uint4*)(g_At + ((size_t)(kc + 16) * MT + mt) * GT_A + sw) = hi4;
}

// W -> B' = [W_h | W_l] fp16 tiles
__global__ __launch_bounds__(256) void convB(const float* __restrict__ W)
{
    int t = blockIdx.x * 256 + threadIdx.x;
    int cg = t & 7;
    int kc = (t >> 3) & 15;
    int n  = t >> 7;

    const float4* wp = (const float4*)(W + (size_t)n * II + kc * 64 + cg * 8);
    float4 v0 = wp[0], v1 = wp[1];
    float f[8] = {v0.x, v0.y, v0.z, v0.w, v1.x, v1.y, v1.z, v1.w};
    float hif[8], lof[8];
#pragma unroll
    for (int i = 0; i < 8; i++) {
        __half h = __float2half_rn(f[i]);
        hif[i] = __half2float(h);
        lof[i] = f[i] - hif[i];
    }
    uint4 hi4 = {pack_h2(hif[0], hif[1]), pack_h2(hif[2], hif[3]),
                 pack_h2(hif[4], hif[5]), pack_h2(hif[6], hif[7])};
    uint4 lo4 = {pack_h2(lof[0], lof[1]), pack_h2(lof[2], lof[3]),
                 pack_h2(lof[4], lof[5]), pack_h2(lof[6], lof[7])};

    int nt = n >> 7, r = n & 127;
    uint32_t off = (uint32_t)r * 128 + cg * 16;
    uint32_t sw  = off ^ ((off >> 3) & 0x70);

    *(uint4*)(g_Bt + ((size_t)(kc +  0) * NTB + nt) * GT_B + sw) = hi4;
    *(uint4*)(g_Bt + ((size_t)(kc + 16) * NTB + nt) * GT_B + sw) = lo4;
}

// ------------------------------------------------------------------
// HMMA pre-GEMM (128x128 CTA, 4 warps of 64x64, 2 CTA/SM), fp16, KCHG=32
// ------------------------------------------------------------------
__device__ __forceinline__ void load_stage(uint32_t sbase, int s, int c, int mt, int nt, int tid)
{
    uint32_t smA = sbase + s * GSTAGE_B;
    uint32_t smB = smA + GT_A;
    const unsigned char* gA = g_At + ((size_t)c * MT + mt) * GT_A;
    const unsigned char* gB = g_Bt + ((size_t)c * NTB + nt) * GT_B;
#pragma unroll
    for (int i = 0; i < 8; i++) {
        uint32_t off = (uint32_t)(tid + i * 128) * 16;
        cp16(smA + off, gA + off);
    }
#pragma unroll
    for (int i = 0; i < 8; i++) {
        uint32_t off = (uint32_t)(tid + i * 128) * 16;
        cp16(smB + off, gB + off);
    }
}

__global__ __launch_bounds__(128, 2) void gemm_mma(const float* __restrict__ bW,
                                                   const float* __restrict__ bR)
{
    extern __shared__ __align__(128) unsigned char smg[];
    const uint32_t sbase = smem_u32(smg);

    const int tid  = threadIdx.x;
    const int lane = tid & 31;
    const int warp = tid >> 5;
    const int wm   = warp & 1;
    const int wn   = warp >> 1;
    const int nt   = blockIdx.x;
    const int mt   = blockIdx.y;

    float acc[4][8][4];
#pragma unroll
    for (int i = 0; i < 4; i++)
#pragma unroll
        for (int j = 0; j < 8; j++)
#pragma unroll
            for (int q = 0; q < 4; q++) acc[i][j][q] = 0.f;

    load_stage(sbase, 0, 0, mt, nt, tid); cp_commit();
    load_stage(sbase, 1, 1, mt, nt, tid); cp_commit();

    const int rl = lane & 15;
    const int chalf = lane >> 4;

#pragma unroll 1
    for (int c = 0; c < KCHG; c++) {
        if (c + 2 < KCHG) load_stage(sbase, (c + 2) % GSTG, c + 2, mt, nt, tid);
        cp_commit();
        cp_wait<2>();
        __syncthreads();

        const uint32_t smA = sbase + (c % GSTG) * GSTAGE_B;
        const uint32_t smB = smA + GT_A;

#pragma unroll
        for (int ks = 0; ks < 4; ks++) {
            const int kb = ks * 32 + chalf * 16;
            uint32_t a[4][4];
#pragma unroll
            for (int i = 0; i < 4; i++) {
                uint32_t off = (uint32_t)(wm * 64 + i * 16 + rl) * 128 + kb;
                ldsm4(a[i], smA + (off ^ ((off >> 3) & 0x70)));
            }
            uint32_t b[4][4];
#pragma unroll
            for (int j = 0; j < 4; j++) {
                uint32_t off = (uint32_t)(wn * 64 + j * 16 + rl) * 128 + kb;
                ldsm4(b[j], smB + (off ^ ((off >> 3) & 0x70)));
            }
#pragma unroll
            for (int i = 0; i < 4; i++)
#pragma unroll
                for (int j = 0; j < 4; j++) {
                    mma16816h(acc[i][2 * j + 0], a[i], b[j][0], b[j][2]);
                    mma16816h(acc[i][2 * j + 1], a[i], b[j][1], b[j][3]);
                }
        }
        __syncthreads();
    }

    const int m0  = mt * 128 + wm * 64 + (lane >> 2);
    const int n0g = nt * 128 + wn * 64;
#pragma unroll
    for (int i = 0; i < 4; i++) {
#pragma unroll
        for (int j = 0; j < 8; j++) {
            int n = n0g + j * 8 + (lane & 3) * 2;
            float bx = bW[n] + bR[n];
            float by = bW[n + 1] + bR[n + 1];
            int r0 = m0 + i * 16;
            float2 o0 = {acc[i][j][0] + bx, acc[i][j][1] + by};
            float2 o1 = {acc[i][j][2] + bx, acc[i][j][3] + by};
            *(float2*)&g_gates[(size_t)r0 * G4 + n] = o0;
            *(float2*)&g_gates[(size_t)(r0 + 8) * G4 + n] = o1;
        }
    }
}

// ------------------------------------------------------------------
// Init: reset counters; y0 -> fp16 buffer
// ------------------------------------------------------------------
__global__ __launch_bounds__(256) void init_kernel(const float* __restrict__ y0)
{
    int i = blockIdx.x * 256 + threadIdx.x;   // 0..32767
    if (i < 16 * 32) g_cnt[i] = 0;
    g_y16[0][i] = __float2half_rn(y0[i]);
}

// ------------------------------------------------------------------
// Persistent tensor-core recurrence, fp16 2-term (R14 winner), with a
// distributed-arrival grid barrier: 16 counters (8-way contention each),
// 16 polling threads per CTA.
// ------------------------------------------------------------------
extern __shared__ __align__(128) unsigned char smrec[];

__device__ __forceinline__ void issue_y_chunk(uint32_t sbase, int buf, int c,
                                              const __half* __restrict__ yg,
                                              int tid)
{
#pragma unroll
    for (int i = 0; i < 4; i++) {
        int gran = tid + i * 256;              // 0..1023
        int bb   = gran >> 5;
        int gi   = gran & 31;
        const __half* src = yg + bb * 1024 + c * 256 + gi * 8;
        uint32_t dst = sbase + YSM + buf * YBUF + bb * 512
                     + (((uint32_t)gi * 16) ^ (((uint32_t)bb & 7) << 4));
        cp16(dst, src);
    }
    cp_commit();
}

__global__ __launch_bounds__(NTH, 1) void lstm_persist(const float* __restrict__ R,
                                                       const float* __restrict__ c0,
                                                       float* __restrict__ yout,
                                                       float* __restrict__ cout)
{
    const int tid = threadIdx.x;
    const int blk = blockIdx.x;
    const uint32_t sbase = smem_u32(smrec);

    // ---- load + split + swizzle R slice into SMEM as fp16 hi/lo (once) ----
    for (int i = tid; i < 4096; i += NTH) {
        int rr  = i >> 7;
        int g16 = i & 127;
        int G   = (rr >> 3) * HH + blk * 8 + (rr & 7);
        const float4* p = (const float4*)(R + (size_t)G * HH + g16 * 8);
        float4 v0 = p[0], v1 = p[1];
        float f[8] = {v0.x, v0.y, v0.z, v0.w, v1.x, v1.y, v1.z, v1.w};
        float hif[8], lof[8];
#pragma unroll
        for (int j = 0; j < 8; j++) {
            __half h = __float2half_rn(f[j]);
            hif[j] = __half2float(h);
            lof[j] = f[j] - hif[j];
        }
        uint4 hi4 = {pack_h2(hif[0], hif[1]), pack_h2(hif[2], hif[3]),
                     pack_h2(hif[4], hif[5]), pack_h2(hif[6], hif[7])};
        uint4 lo4 = {pack_h2(lof[0], lof[1]), pack_h2(lof[2], lof[3]),
                     pack_h2(lof[4], lof[5]), pack_h2(lof[6], lof[7])};
        uint32_t off = (uint32_t)rr * 2048 + (((uint32_t)g16 * 16) ^ (((uint32_t)rr & 7) << 4));
        *(uint4*)(smrec + RS_H + off) = hi4;
        *(uint4*)(smrec + RS_L + off) = lo4;
    }
    __syncthreads();

    const int lane  = tid & 31;
    const int warp  = tid >> 5;
    const int wn    = warp & 1;        // n half (16 rows)
    const int wk    = warp >> 1;       // k quarter
    const int l15   = lane & 15;
    const int chalf = lane >> 4;

    const int b  = tid >> 3;
    const int hl = tid & 7;
    const int h  = blk * 8 + hl;

    float c_val = c0[(size_t)b * HH + h];

    const uint32_t aswz = (uint32_t)(l15 & 7) << 4;
    const uint32_t nrow = (uint32_t)(wn * 16 + l15);
    const uint32_t nswz = (nrow & 7) << 4;
    const uint32_t rbh  = sbase + RS_H + nrow * 2048;
    const uint32_t rbl  = sbase + RS_L + nrow * 2048;

    for (int t = 0; t < TT; t++) {
        const int rbuf = t & 1;
        const __half* yg = g_y16[rbuf];

        const float* gp = g_gates + (size_t)t * BB * G4 + (size_t)b * G4 + h;
        float gp0 = gp[0 * HH], gp1 = gp[1 * HH], gp2 = gp[2 * HH], gp3 = gp[3 * HH];

        float acc00[4] = {0.f, 0.f, 0.f, 0.f};
        float acc01[4] = {0.f, 0.f, 0.f, 0.f};
        float acc10[4] = {0.f, 0.f, 0.f, 0.f};
        float acc11[4] = {0.f, 0.f, 0.f, 0.f};

        issue_y_chunk(sbase, 0, 0, yg, tid);

#pragma unroll
        for (int c = 0; c < 4; c++) {
            cp_wait<0>();
            __syncthreads();
            if (c < 3) issue_y_chunk(sbase, (c + 1) & 1, c + 1, yg, tid);

            const uint32_t yb = sbase + YSM + (c & 1) * YBUF;
            const uint32_t a0b = yb + (uint32_t)l15 * 512;
            const uint32_t a1b = yb + (uint32_t)(16 + l15) * 512;

#pragma unroll
            for (int s = 0; s < 4; s++) {
                const uint32_t sa   = (uint32_t)(wk * 4 + s);
                const uint32_t aoff = sa * 32 + chalf * 16;
                const uint32_t koff = (uint32_t)c * 512 + aoff;
                uint32_t a0[4], a1[4], bh[4], bl[4];
                ldsm4(a0, a0b + (aoff ^ aswz));
                ldsm4(a1, a1b + (aoff ^ aswz));
                ldsm4(bh, rbh + (koff ^ nswz));
                ldsm4(bl, rbl + (koff ^ nswz));
                mma16816h(acc00, a0, bh[0], bh[2]);
                mma16816h(acc01, a0, bh[1], bh[3]);
                mma16816h(acc10, a1, bh[0], bh[2]);
                mma16816h(acc11, a1, bh[1], bh[3]);
                mma16816h(acc00, a0, bl[0], bl[2]);
                mma16816h(acc01, a0, bl[1], bl[3]);
                mma16816h(acc10, a1, bl[0], bl[2]);
                mma16816h(acc11, a1, bl[1], bl[3]);
            }
        }

        // ---- per-warp partial write (4 gsm arrays, by wk) ----
        {
            float* gsmk = (float*)(smrec + GSM + wk * 4224);
            const int mrow = lane >> 2;
            const int nb0  = wn * 16 + (lane & 3) * 2;
            gsmk[(nb0 + 0) * 33 + mrow]      = acc00[0];
            gsmk[(nb0 + 1) * 33 + mrow]      = acc00[1];
            gsmk[(nb0 + 0) * 33 + mrow + 8]  = acc00[2];
            gsmk[(nb0 + 1) * 33 + mrow + 8]  = acc00[3];
            gsmk[(nb0 + 8) * 33 + mrow]      = acc01[0];
            gsmk[(nb0 + 9) * 33 + mrow]      = acc01[1];
            gsmk[(nb0 + 8) * 33 + mrow + 8]  = acc01[2];
            gsmk[(nb0 + 9) * 33 + mrow + 8]  = acc01[3];
            gsmk[(nb0 + 0) * 33 + mrow + 16] = acc10[0];
            gsmk[(nb0 + 1) * 33 + mrow + 16] = acc10[1];
            gsmk[(nb0 + 0) * 33 + mrow + 24] = acc10[2];
            gsmk[(nb0 + 1) * 33 + mrow + 24] = acc10[3];
            gsmk[(nb0 + 8) * 33 + mrow + 16] = acc11[0];
            gsmk[(nb0 + 9) * 33 + mrow + 16] = acc11[1];
            gsmk[(nb0 + 8) * 33 + mrow + 24] = acc11[2];
            gsmk[(nb0 + 9) * 33 + mrow + 24] = acc11[3];
        }
        __syncthreads();

        // ---- gate epilogue (all 256 threads) ----
        {
            float si = gp0, sf = gp1, sz = gp2, so4 = gp3;
#pragma unroll
            for (int q = 0; q < 4; q++) {
                const float* gq = (const float*)(smrec + GSM + q * 4224);
                si  += gq[(0 * 8 + hl) * 33 + b];
                sf  += gq[(1 * 8 + hl) * 33 + b];
                sz  += gq[(2 * 8 + hl) * 33 + b];
                so4 += gq[(3 * 8 + hl) * 33 + b];
            }
            float i_ = hsig(si);
            float f_ = hsig(sf);
            float z_ = htanh(sz);
            float o_ = hsig(so4);
            c_val = f_ * c_val + i_ * z_;
            float y_ = o_ * htanh(c_val);

            size_t oidx = (size_t)t * BB * HH + (size_t)b * HH + h;
            yout[oidx] = y_;
            cout[oidx] = c_val;

            g_y16[(t + 1) & 1][b * HH + h] = __float2half_rn(y_);
        }

        // ---- distributed grid barrier ----
        if (t < TT - 1) {
            __syncthreads();                   // y stores done
            if (tid == 0) {
                __threadfence();
                atomicAdd(&g_cnt[(blk >> 3) * 32], 1u);
            }
            if (tid < 16) {
                const unsigned tgt = 8u * (unsigned)(t + 1);
                unsigned v;
                do {
                    asm volatile("ld.acquire.gpu.global.u32 %0, [%1];"
                                 : "=r"(v) : "l"(&g_cnt[tid * 32]) : "memory");
                } while (v < tgt);
            }
            __syncthreads();
        }
    }
}

// ------------------------------------------------------------------
extern "C" void kernel_launch(void* const* d_in, const int* in_sizes, int n_in,
                              void* d_out, int out_size)
{
    const float* y0 = (const float*)d_in[0];
    const float* c0 = (const float*)d_in[1];
    const float* x  = (const float*)d_in[2];
    const float* W  = (const float*)d_in[3];
    const float* R  = (const float*)d_in[4];
    const float* bW = (const float*)d_in[5];
    const float* bR = (const float*)d_in[6];

    float* yout = (float*)d_out;
    float* cout = yout + (size_t)TT * BB * HH;

    const int smem_gemm = GSTG * GSTAGE_B;     // 98304
    cudaFuncSetAttribute(gemm_mma, cudaFuncAttributeMaxDynamicSharedMemorySize, smem_gemm);
    cudaFuncSetAttribute(lstm_persist, cudaFuncAttributeMaxDynamicSharedMemorySize, SMEM_REC);

    convA<<<8192, 256>>>(x);
    convB<<<2048, 256>>>(W);
    init_kernel<<<128, 256>>>(y0);
    gemm_mma<<<dim3(NTB, MT), 128, smem_gemm>>>(bW, bR);
    lstm_persist<<<NB, NTH, SMEM_REC>>>(R, c0, yout, cout);
}

// round 17
// speedup vs baseline: 1.4161x; 1.0073x over previous
#include <cuda_runtime.h>
#include <cuda_bf16.h>
#include <cuda_fp16.h>
#include <cstdint>

#define TT 512
#define BB 32
#define II 1024
#define HH 1024
#define G4 4096   // 4*H
#define NB 128    // persistent CTAs
#define NTH 256   // threads per CTA (recurrence)

#define KCHG 32         // gemm K' chunks of 64 (2*1024/64), fp16 2-term
#define MT  128         // A blobs per chunk (16384/128)
#define NTB 32          // B blobs per chunk (4096/128)
#define GT_A 16384
#define GT_B 16384
#define GSTAGE_B (GT_A + GT_B)   // 32768
#define GSTG 3

// recurrence smem offsets (bytes)
#define RS_H 0                      // R hi fp16: 32 rows x 1024 k = 64KB
#define RS_L 65536                  // R lo fp16: 64KB
#define YSM  131072                 // y fp16: 2 buf x 16KB
#define YBUF 16384
#define GSM  163840                 // 4 arrays of [32][33] floats (4224B each)
#define SMEM_REC (GSM + 4 * 4224)

// ------------------------- device scratch -------------------------
__device__ float g_gates[(size_t)TT * BB * G4];                 // 256 MB
__device__ unsigned char g_At[(size_t)KCHG * MT * GT_A];        // 64 MB
__device__ unsigned char g_Bt[(size_t)KCHG * NTB * GT_B];       // 16 MB
__device__ __half g_y16[2][BB * HH];         // y fp16, [buf][b][k]
__device__ unsigned g_cnt[16 * 32];          // 16 counters, 128B apart

// ------------------------- helpers -------------------------
__device__ __forceinline__ uint32_t smem_u32(const void* p) {
    uint32_t a;
    asm("{ .reg .u64 t; cvta.to.shared.u64 t, %1; cvt.u32.u64 %0, t; }" : "=r"(a) : "l"(p));
    return a;
}
__device__ __forceinline__ void ldsm4(uint32_t (&r)[4], uint32_t addr) {
    asm volatile("ldmatrix.sync.aligned.m8n8.x4.shared.b16 {%0,%1,%2,%3}, [%4];"
        : "=r"(r[0]), "=r"(r[1]), "=r"(r[2]), "=r"(r[3]) : "r"(addr));
}
__device__ __forceinline__ void mma16816h(float (&d)[4], const uint32_t (&a)[4],
                                          uint32_t b0, uint32_t b1) {
    asm volatile("mma.sync.aligned.m16n8k16.row.col.f32.f16.f16.f32 "
        "{%0,%1,%2,%3}, {%4,%5,%6,%7}, {%8,%9}, {%0,%1,%2,%3};"
        : "+f"(d[0]), "+f"(d[1]), "+f"(d[2]), "+f"(d[3])
        : "r"(a[0]), "r"(a[1]), "r"(a[2]), "r"(a[3]), "r"(b0), "r"(b1));
}
__device__ __forceinline__ void cp16(uint32_t sdst, const void* gsrc) {
    asm volatile("cp.async.cg.shared.global [%0], [%1], 16;" :: "r"(sdst), "l"(gsrc) : "memory");
}
__device__ __forceinline__ void cp_commit() {
    asm volatile("cp.async.commit_group;" ::: "memory");
}
template<int N> __device__ __forceinline__ void cp_wait() {
    asm volatile("cp.async.wait_group %0;" :: "n"(N) : "memory");
}
__device__ __forceinline__ uint32_t pack_h2(float a, float b) {
    __half2 h = __floats2half2_rn(a, b);
    return *(uint32_t*)&h;
}
__device__ __forceinline__ float hsig(float v) {
    return __saturatef(v * 0.16666666666666666f + 0.5f);
}
__device__ __forceinline__ float htanh(float v) {
    return fminf(fmaxf(v, -1.f), 1.f);
}

// ------------------------------------------------------------------
// Conversion: x -> A' = [x_h | x_h] fp16 tiles (128x64), SW128 swizzle
// ------------------------------------------------------------------
__global__ __launch_bounds__(256) void convA(const float* __restrict__ x)
{
    int t = blockIdx.x * 256 + threadIdx.x;
    int cg = t & 7;
    int kc = (t >> 3) & 15;
    int m  = t >> 7;

    const float4* xp = (const float4*)(x + (size_t)m * II + kc * 64 + cg * 8);
    float4 v0 = xp[0], v1 = xp[1];
    float f[8] = {v0.x, v0.y, v0.z, v0.w, v1.x, v1.y, v1.z, v1.w};
    uint4 hi4 = {pack_h2(f[0], f[1]), pack_h2(f[2], f[3]),
                 pack_h2(f[4], f[5]), pack_h2(f[6], f[7])};

    int mt = m >> 7, r = m & 127;
    uint32_t off = (uint32_t)r * 128 + cg * 16;
    uint32_t sw  = off ^ ((off >> 3) & 0x70);

    *(uint4*)(g_At + ((size_t)(kc +  0) * MT + mt) * GT_A + sw) = hi4;
    *(uint4*)(g_At + ((size_t)(kc + 16) * MT + mt) * GT_A + sw) = hi4;
}

// W -> B' = [W_h | W_l] fp16 tiles
__global__ __launch_bounds__(256) void convB(const float* __restrict__ W)
{
    int t = blockIdx.x * 256 + threadIdx.x;
    int cg = t & 7;
    int kc = (t >> 3) & 15;
    int n  = t >> 7;

    const float4* wp = (const float4*)(W + (size_t)n * II + kc * 64 + cg * 8);
    float4 v0 = wp[0], v1 = wp[1];
    float f[8] = {v0.x, v0.y, v0.z, v0.w, v1.x, v1.y, v1.z, v1.w};
    float hif[8], lof[8];
#pragma unroll
    for (int i = 0; i < 8; i++) {
        __half h = __float2half_rn(f[i]);
        hif[i] = __half2float(h);
        lof[i] = f[i] - hif[i];
    }
    uint4 hi4 = {pack_h2(hif[0], hif[1]), pack_h2(hif[2], hif[3]),
                 pack_h2(hif[4], hif[5]), pack_h2(hif[6], hif[7])};
    uint4 lo4 = {pack_h2(lof[0], lof[1]), pack_h2(lof[2], lof[3]),
                 pack_h2(lof[4], lof[5]), pack_h2(lof[6], lof[7])};

    int nt = n >> 7, r = n & 127;
    uint32_t off = (uint32_t)r * 128 + cg * 16;
    uint32_t sw  = off ^ ((off >> 3) & 0x70);

    *(uint4*)(g_Bt + ((size_t)(kc +  0) * NTB + nt) * GT_B + sw) = hi4;
    *(uint4*)(g_Bt + ((size_t)(kc + 16) * NTB + nt) * GT_B + sw) = lo4;
}

// ------------------------------------------------------------------
// HMMA pre-GEMM (128x128 CTA, 4 warps of 64x64, 2 CTA/SM), fp16, KCHG=32
// ------------------------------------------------------------------
__device__ __forceinline__ void load_stage(uint32_t sbase, int s, int c, int mt, int nt, int tid)
{
    uint32_t smA = sbase + s * GSTAGE_B;
    uint32_t smB = smA + GT_A;
    const unsigned char* gA = g_At + ((size_t)c * MT + mt) * GT_A;
    const unsigned char* gB = g_Bt + ((size_t)c * NTB + nt) * GT_B;
#pragma unroll
    for (int i = 0; i < 8; i++) {
        uint32_t off = (uint32_t)(tid + i * 128) * 16;
        cp16(smA + off, gA + off);
    }
#pragma unroll
    for (int i = 0; i < 8; i++) {
        uint32_t off = (uint32_t)(tid + i * 128) * 16;
        cp16(smB + off, gB + off);
    }
}

__global__ __launch_bounds__(128, 2) void gemm_mma(const float* __restrict__ bW,
                                                   const float* __restrict__ bR)
{
    extern __shared__ __align__(128) unsigned char smg[];
    const uint32_t sbase = smem_u32(smg);

    const int tid  = threadIdx.x;
    const int lane = tid & 31;
    const int warp = tid >> 5;
    const int wm   = warp & 1;
    const int wn   = warp >> 1;
    const int nt   = blockIdx.x;
    const int mt   = blockIdx.y;

    float acc[4][8][4];
#pragma unroll
    for (int i = 0; i < 4; i++)
#pragma unroll
        for (int j = 0; j < 8; j++)
#pragma unroll
            for (int q = 0; q < 4; q++) acc[i][j][q] = 0.f;

    load_stage(sbase, 0, 0, mt, nt, tid); cp_commit();
    load_stage(sbase, 1, 1, mt, nt, tid); cp_commit();

    const int rl = lane & 15;
    const int chalf = lane >> 4;

#pragma unroll 1
    for (int c = 0; c < KCHG; c++) {
        if (c + 2 < KCHG) load_stage(sbase, (c + 2) % GSTG, c + 2, mt, nt, tid);
        cp_commit();
        cp_wait<2>();
        __syncthreads();

        const uint32_t smA = sbase + (c % GSTG) * GSTAGE_B;
        const uint32_t smB = smA + GT_A;

#pragma unroll
        for (int ks = 0; ks < 4; ks++) {
            const int kb = ks * 32 + chalf * 16;
            uint32_t a[4][4];
#pragma unroll
            for (int i = 0; i < 4; i++) {
                uint32_t off = (uint32_t)(wm * 64 + i * 16 + rl) * 128 + kb;
                ldsm4(a[i], smA + (off ^ ((off >> 3) & 0x70)));
            }
            uint32_t b[4][4];
#pragma unroll
            for (int j = 0; j < 4; j++) {
                uint32_t off = (uint32_t)(wn * 64 + j * 16 + rl) * 128 + kb;
                ldsm4(b[j], smB + (off ^ ((off >> 3) & 0x70)));
            }
#pragma unroll
            for (int i = 0; i < 4; i++)
#pragma unroll
                for (int j = 0; j < 4; j++) {
                    mma16816h(acc[i][2 * j + 0], a[i], b[j][0], b[j][2]);
                    mma16816h(acc[i][2 * j + 1], a[i], b[j][1], b[j][3]);
                }
        }
        __syncthreads();
    }

    const int m0  = mt * 128 + wm * 64 + (lane >> 2);
    const int n0g = nt * 128 + wn * 64;
#pragma unroll
    for (int i = 0; i < 4; i++) {
#pragma unroll
        for (int j = 0; j < 8; j++) {
            int n = n0g + j * 8 + (lane & 3) * 2;
            float bx = bW[n] + bR[n];
            float by = bW[n + 1] + bR[n + 1];
            int r0 = m0 + i * 16;
            float2 o0 = {acc[i][j][0] + bx, acc[i][j][1] + by};
            float2 o1 = {acc[i][j][2] + bx, acc[i][j][3] + by};
            *(float2*)&g_gates[(size_t)r0 * G4 + n] = o0;
            *(float2*)&g_gates[(size_t)(r0 + 8) * G4 + n] = o1;
        }
    }
}

// ------------------------------------------------------------------
// Init: reset counters; y0 -> fp16 buffer
// ------------------------------------------------------------------
__global__ __launch_bounds__(256) void init_kernel(const float* __restrict__ y0)
{
    int i = blockIdx.x * 256 + threadIdx.x;   // 0..32767
    if (i < 16 * 32) g_cnt[i] = 0;
    g_y16[0][i] = __float2half_rn(y0[i]);
}

// ------------------------------------------------------------------
// Persistent tensor-core recurrence, fp16 2-term, R fragments hoisted
// into registers (constant across all 512 steps). Per-step smem reads
// are y fragments only.
// ------------------------------------------------------------------
extern __shared__ __align__(128) unsigned char smrec[];

__device__ __forceinline__ void issue_y_chunk(uint32_t sbase, int buf, int c,
                                              const __half* __restrict__ yg,
                                              int tid)
{
#pragma unroll
    for (int i = 0; i < 4; i++) {
        int gran = tid + i * 256;              // 0..1023
        int bb   = gran >> 5;
        int gi   = gran & 31;
        const __half* src = yg + bb * 1024 + c * 256 + gi * 8;
        uint32_t dst = sbase + YSM + buf * YBUF + bb * 512
                     + (((uint32_t)gi * 16) ^ (((uint32_t)bb & 7) << 4));
        cp16(dst, src);
    }
    cp_commit();
}

__global__ __launch_bounds__(NTH, 1) void lstm_persist(const float* __restrict__ R,
                                                       const float* __restrict__ c0,
                                                       float* __restrict__ yout,
                                                       float* __restrict__ cout)
{
    const int tid = threadIdx.x;
    const int blk = blockIdx.x;
    const uint32_t sbase = smem_u32(smrec);

    // ---- load + split + swizzle R slice into SMEM as fp16 hi/lo (once) ----
    for (int i = tid; i < 4096; i += NTH) {
        int rr  = i >> 7;
        int g16 = i & 127;
        int G   = (rr >> 3) * HH + blk * 8 + (rr & 7);
        const float4* p = (const float4*)(R + (size_t)G * HH + g16 * 8);
        float4 v0 = p[0], v1 = p[1];
        float f[8] = {v0.x, v0.y, v0.z, v0.w, v1.x, v1.y, v1.z, v1.w};
        float hif[8], lof[8];
#pragma unroll
        for (int j = 0; j < 8; j++) {
            __half h = __float2half_rn(f[j]);
            hif[j] = __half2float(h);
            lof[j] = f[j] - hif[j];
        }
        uint4 hi4 = {pack_h2(hif[0], hif[1]), pack_h2(hif[2], hif[3]),
                     pack_h2(hif[4], hif[5]), pack_h2(hif[6], hif[7])};
        uint4 lo4 = {pack_h2(lof[0], lof[1]), pack_h2(lof[2], lof[3]),
                     pack_h2(lof[4], lof[5]), pack_h2(lof[6], lof[7])};
        uint32_t off = (uint32_t)rr * 2048 + (((uint32_t)g16 * 16) ^ (((uint32_t)rr & 7) << 4));
        *(uint4*)(smrec + RS_H + off) = hi4;
        *(uint4*)(smrec + RS_L + off) = lo4;
    }
    __syncthreads();

    const int lane  = tid & 31;
    const int warp  = tid >> 5;
    const int wn    = warp & 1;        // n half (16 rows)
    const int wk    = warp >> 1;       // k quarter
    const int l15   = lane & 15;
    const int chalf = lane >> 4;

    const int b  = tid >> 3;
    const int hl = tid & 7;
    const int h  = blk * 8 + hl;

    float c_val = c0[(size_t)b * HH + h];

    const uint32_t aswz = (uint32_t)(l15 & 7) << 4;
    const uint32_t nrow = (uint32_t)(wn * 16 + l15);
    const uint32_t nswz = (nrow & 7) << 4;
    const uint32_t rbh  = sbase + RS_H + nrow * 2048;
    const uint32_t rbl  = sbase + RS_L + nrow * 2048;

    // ---- hoist R fragments into registers (constant across steps) ----
    uint32_t Bh[16][4], Bl[16][4];
#pragma unroll
    for (int c = 0; c < 4; c++)
#pragma unroll
        for (int s = 0; s < 4; s++) {
            const uint32_t aoff = (uint32_t)((wk * 4 + s) * 32 + chalf * 16);
            const uint32_t koff = (uint32_t)c * 512 + aoff;
            ldsm4(Bh[c * 4 + s], rbh + (koff ^ nswz));
            ldsm4(Bl[c * 4 + s], rbl + (koff ^ nswz));
        }

    for (int t = 0; t < TT; t++) {
        const int rbuf = t & 1;
        const __half* yg = g_y16[rbuf];

        const float* gp = g_gates + (size_t)t * BB * G4 + (size_t)b * G4 + h;
        float gp0 = gp[0 * HH], gp1 = gp[1 * HH], gp2 = gp[2 * HH], gp3 = gp[3 * HH];

        float acc00[4] = {0.f, 0.f, 0.f, 0.f};
        float acc01[4] = {0.f, 0.f, 0.f, 0.f};
        float acc10[4] = {0.f, 0.f, 0.f, 0.f};
        float acc11[4] = {0.f, 0.f, 0.f, 0.f};

        issue_y_chunk(sbase, 0, 0, yg, tid);

#pragma unroll
        for (int c = 0; c < 4; c++) {
            cp_wait<0>();
            __syncthreads();
            if (c < 3) issue_y_chunk(sbase, (c + 1) & 1, c + 1, yg, tid);

            const uint32_t yb = sbase + YSM + (c & 1) * YBUF;
            const uint32_t a0b = yb + (uint32_t)l15 * 512;
            const uint32_t a1b = yb + (uint32_t)(16 + l15) * 512;

#pragma unroll
            for (int s = 0; s < 4; s++) {
                const uint32_t aoff = (uint32_t)((wk * 4 + s) * 32 + chalf * 16);
                uint32_t a0[4], a1[4];
                ldsm4(a0, a0b + (aoff ^ aswz));
                ldsm4(a1, a1b + (aoff ^ aswz));
                mma16816h(acc00, a0, Bh[c * 4 + s][0], Bh[c * 4 + s][2]);
                mma16816h(acc01, a0, Bh[c * 4 + s][1], Bh[c * 4 + s][3]);
                mma16816h(acc10, a1, Bh[c * 4 + s][0], Bh[c * 4 + s][2]);
                mma16816h(acc11, a1, Bh[c * 4 + s][1], Bh[c * 4 + s][3]);
                mma16816h(acc00, a0, Bl[c * 4 + s][0], Bl[c * 4 + s][2]);
                mma16816h(acc01, a0, Bl[c * 4 + s][1], Bl[c * 4 + s][3]);
                mma16816h(acc10, a1, Bl[c * 4 + s][0], Bl[c * 4 + s][2]);
                mma16816h(acc11, a1, Bl[c * 4 + s][1], Bl[c * 4 + s][3]);
            }
        }

        // ---- per-warp partial write (4 gsm arrays, by wk) ----
        {
            float* gsmk = (float*)(smrec + GSM + wk * 4224);
            const int mrow = lane >> 2;
            const int nb0  = wn * 16 + (lane & 3) * 2;
            gsmk[(nb0 + 0) * 33 + mrow]      = acc00[0];
            gsmk[(nb0 + 1) * 33 + mrow]      = acc00[1];
            gsmk[(nb0 + 0) * 33 + mrow + 8]  = acc00[2];
            gsmk[(nb0 + 1) * 33 + mrow + 8]  = acc00[3];
            gsmk[(nb0 + 8) * 33 + mrow]      = acc01[0];
            gsmk[(nb0 + 9) * 33 + mrow]      = acc01[1];
            gsmk[(nb0 + 8) * 33 + mrow + 8]  = acc01[2];
            gsmk[(nb0 + 9) * 33 + mrow + 8]  = acc01[3];
            gsmk[(nb0 + 0) * 33 + mrow + 16] = acc10[0];
            gsmk[(nb0 + 1) * 33 + mrow + 16] = acc10[1];
            gsmk[(nb0 + 0) * 33 + mrow + 24] = acc10[2];
            gsmk[(nb0 + 1) * 33 + mrow + 24] = acc10[3];
            gsmk[(nb0 + 8) * 33 + mrow + 16] = acc11[0];
            gsmk[(nb0 + 9) * 33 + mrow + 16] = acc11[1];
            gsmk[(nb0 + 8) * 33 + mrow + 24] = acc11[2];
            gsmk[(nb0 + 9) * 33 + mrow + 24] = acc11[3];
        }
        __syncthreads();

        // ---- gate epilogue (all 256 threads) ----
        {
            float si = gp0, sf = gp1, sz = gp2, so4 = gp3;
#pragma unroll
            for (int q = 0; q < 4; q++) {
                const float* gq = (const float*)(smrec + GSM + q * 4224);
                si  += gq[(0 * 8 + hl) * 33 + b];
                sf  += gq[(1 * 8 + hl) * 33 + b];
                sz  += gq[(2 * 8 + hl) * 33 + b];
                so4 += gq[(3 * 8 + hl) * 33 + b];
            }
            float i_ = hsig(si);
            float f_ = hsig(sf);
            float z_ = htanh(sz);
            float o_ = hsig(so4);
            c_val = f_ * c_val + i_ * z_;
            float y_ = o_ * htanh(c_val);

            size_t oidx = (size_t)t * BB * HH + (size_t)b * HH + h;
            yout[oidx] = y_;
            cout[oidx] = c_val;

            g_y16[(t + 1) & 1][b * HH + h] = __float2half_rn(y_);
        }

        // ---- distributed grid barrier ----
        if (t < TT - 1) {
            __syncthreads();                   // y stores done
            if (tid == 0) {
                __threadfence();
                atomicAdd(&g_cnt[(blk >> 3) * 32], 1u);
            }
            if (tid < 16) {
                const unsigned tgt = 8u * (unsigned)(t + 1);
                unsigned v;
                do {
                    asm volatile("ld.acquire.gpu.global.u32 %0, [%1];"
                                 : "=r"(v) : "l"(&g_cnt[tid * 32]) : "memory");
                } while (v < tgt);
            }
            __syncthreads();
        }
    }
}

// ------------------------------------------------------------------
extern "C" void kernel_launch(void* const* d_in, const int* in_sizes, int n_in,
                              void* d_out, int out_size)
{
    const float* y0 = (const float*)d_in[0];
    const float* c0 = (const float*)d_in[1];
    const float* x  = (const float*)d_in[2];
    const float* W  = (const float*)d_in[3];
    const float* R  = (const float*)d_in[4];
    const float* bW = (const float*)d_in[5];
    const float* bR = (const float*)d_in[6];

    float* yout = (float*)d_out;
    float* cout = yout + (size_t)TT * BB * HH;

    const int smem_gemm = GSTG * GSTAGE_B;     // 98304
    cudaFuncSetAttribute(gemm_mma, cudaFuncAttributeMaxDynamicSharedMemorySize, smem_gemm);
    cudaFuncSetAttribute(lstm_persist, cudaFuncAttributeMaxDynamicSharedMemorySize, SMEM_REC);

    convA<<<8192, 256>>>(x);
    convB<<<2048, 256>>>(W);
    init_kernel<<<128, 256>>>(y0);
    gemm_mma<<<dim3(NTB, MT), 128, smem_gemm>>>(bW, bR);
    lstm_persist<<<NB, NTH, SMEM_REC>>>(R, c0, yout, cout);
}